// round 1
// baseline (speedup 1.0000x reference)
#include <cuda_runtime.h>
#include <math.h>

// ---------------- problem constants ----------------
#define NA 50000        // num authors
#define NP 50000        // num papers
#define EDG 400000      // edges per relation
#define KH 8            // heads
#define DH 32           // dim per head
#define KD 256          // KH*DH
#define IN_DIM 256
#define SLOPE 0.2f

// ---------------- device scratch (static, no allocation) ----------------
__device__ float g_PA[NA * KD];          // feats_author @ W_micro_author
__device__ float g_PP[NP * KD];          // feats_paper  @ W_micro_paper

__device__ float g_elA_aA[NA * KH];      // el: P_author with attn_author[:, :D]
__device__ float g_erP_aA[NP * KH];      // er: P_paper  with attn_author[:, D:]
__device__ float g_elP_aP[NP * KH];      // el: P_paper  with attn_paper [:, :D]
__device__ float g_erA_aP[NA * KH];      // er: P_author with attn_paper [:, D:]
__device__ float g_erP_aP[NP * KH];      // er: P_paper  with attn_paper [:, D:]

__device__ unsigned g_m_w[NP * KH];      // segment max (encoded) writes  (dst=paper)
__device__ unsigned g_m_wb[NA * KH];     // written_by (dst=author)
__device__ unsigned g_m_c[NP * KH];      // cites (dst=paper)
__device__ float    g_s_w[NP * KH];
__device__ float    g_s_wb[NA * KH];
__device__ float    g_s_c[NP * KH];
__device__ float    g_ft_w[NP * KD];     // unnormalized aggregation -> r after norm
__device__ float    g_ft_wb[NA * KD];
__device__ float    g_ft_c[NP * KD];

__device__ float g_rf_w[NP * KD];        // r_writes @ W_macro_rel_writes
__device__ float g_rf_wb[NA * KD];
__device__ float g_rf_c[NP * KD];
__device__ float g_nodeP[NP * KD];       // feats_paper @ W_macro_node_paper

// ---------------- helpers ----------------
__device__ __forceinline__ unsigned enc_f(float f) {
    unsigned u = __float_as_uint(f);
    return u ^ ((unsigned)((int)u >> 31) | 0x80000000u);
}
__device__ __forceinline__ float dec_f(unsigned u) {
    return (u & 0x80000000u) ? __uint_as_float(u ^ 0x80000000u)
                             : __uint_as_float(~u);
}
__device__ __forceinline__ float leaky(float v) {
    return v > 0.f ? v : SLOPE * v;
}

// ---------------- GEMM: C[M,256] = A[M,256] @ B[256,256] (+bias) ----------------
// 128x128 tile, BK=8, 256 threads, 8x8 microtile.
__global__ void gemm128(const float* __restrict__ A, const float* __restrict__ B,
                        const float* __restrict__ bias, float* __restrict__ C, int M)
{
    __shared__ float As[8][128];
    __shared__ float Bs[8][128];
    const int m0 = blockIdx.x * 128;
    const int n0 = blockIdx.y * 128;
    const int tid = threadIdx.x;
    const int trow = (tid >> 4) << 3;   // 0..120
    const int tcol = (tid & 15) << 3;   // 0..120

    float acc[8][8];
#pragma unroll
    for (int i = 0; i < 8; i++)
#pragma unroll
        for (int j = 0; j < 8; j++) acc[i][j] = 0.f;

    const int arow = tid >> 1;          // 0..127
    const int aq   = (tid & 1) << 2;    // 0 or 4
    const int bk   = tid >> 5;          // 0..7
    const int bn   = (tid & 31) << 2;   // 0..124

    for (int k0 = 0; k0 < KD; k0 += 8) {
        float4 av;
        if (m0 + arow < M) av = *(const float4*)&A[(size_t)(m0 + arow) * KD + k0 + aq];
        else av = make_float4(0.f, 0.f, 0.f, 0.f);
        As[aq + 0][arow] = av.x;
        As[aq + 1][arow] = av.y;
        As[aq + 2][arow] = av.z;
        As[aq + 3][arow] = av.w;
        *(float4*)&Bs[bk][bn] = *(const float4*)&B[(size_t)(k0 + bk) * KD + n0 + bn];
        __syncthreads();
#pragma unroll
        for (int kk = 0; kk < 8; kk++) {
            float a[8], b[8];
            *(float4*)&a[0] = *(const float4*)&As[kk][trow];
            *(float4*)&a[4] = *(const float4*)&As[kk][trow + 4];
            *(float4*)&b[0] = *(const float4*)&Bs[kk][tcol];
            *(float4*)&b[4] = *(const float4*)&Bs[kk][tcol + 4];
#pragma unroll
            for (int i = 0; i < 8; i++)
#pragma unroll
                for (int j = 0; j < 8; j++)
                    acc[i][j] = fmaf(a[i], b[j], acc[i][j]);
        }
        __syncthreads();
    }
#pragma unroll
    for (int i = 0; i < 8; i++) {
        int r = m0 + trow + i;
        if (r < M) {
#pragma unroll
            for (int j = 0; j < 8; j += 4) {
                float4 o;
                o.x = acc[i][j + 0]; o.y = acc[i][j + 1];
                o.z = acc[i][j + 2]; o.w = acc[i][j + 3];
                if (bias) {
                    o.x += bias[n0 + tcol + j + 0];
                    o.y += bias[n0 + tcol + j + 1];
                    o.z += bias[n0 + tcol + j + 2];
                    o.w += bias[n0 + tcol + j + 3];
                }
                *(float4*)&C[(size_t)r * KD + n0 + tcol + j] = o;
            }
        }
    }
}

// ---------------- attention dot: out[n,k] = sum_d P[n,k*32+d]*attn[k*64+off+d] ----------------
__global__ void attn_dot(const float* __restrict__ P, const float* __restrict__ attn,
                         int off, float* __restrict__ out)
{
    int n = blockIdx.x;
    int k = threadIdx.x >> 5;
    int lane = threadIdx.x & 31;
    float v = P[(size_t)n * KD + k * DH + lane] * attn[k * 64 + off + lane];
#pragma unroll
    for (int s = 16; s > 0; s >>= 1) v += __shfl_xor_sync(0xffffffffu, v, s);
    if (lane == 0) out[n * KH + k] = v;
}

// ---------------- init: zero m/s/ft for all 3 relations ----------------
__global__ void init_buffers()
{
    int tid = blockIdx.x * blockDim.x + threadIdx.x;
    if (tid < NP * KD) { g_ft_w[tid] = 0.f; g_ft_c[tid] = 0.f; }
    if (tid < NA * KD) { g_ft_wb[tid] = 0.f; }
    if (tid < NP * KH) { g_m_w[tid] = 0u; g_m_c[tid] = 0u; g_s_w[tid] = 0.f; g_s_c[tid] = 0.f; }
    if (tid < NA * KH) { g_m_wb[tid] = 0u; g_s_wb[tid] = 0.f; }
}

// ---------------- edge pass 1: segment max via encoded atomicMax ----------------
__global__ void edge_max(const int* __restrict__ src, const int* __restrict__ dst,
                         const float* __restrict__ el, const float* __restrict__ er,
                         unsigned* __restrict__ menc)
{
    int e = blockIdx.x * blockDim.x + threadIdx.x;
    if (e >= EDG) return;
    int s = src[e], d = dst[e];
    float4 l0 = *(const float4*)&el[s * KH];
    float4 l1 = *(const float4*)&el[s * KH + 4];
    float4 r0 = *(const float4*)&er[d * KH];
    float4 r1 = *(const float4*)&er[d * KH + 4];
    float vs[8] = { l0.x + r0.x, l0.y + r0.y, l0.z + r0.z, l0.w + r0.w,
                    l1.x + r1.x, l1.y + r1.y, l1.z + r1.z, l1.w + r1.w };
#pragma unroll
    for (int k = 0; k < 8; k++)
        atomicMax(&menc[d * KH + k], enc_f(leaky(vs[k])));
}

// ---------------- edge pass 2: ex=exp(e-m); s += ex; ft += ex * fs[src] ----------------
// one warp per edge
__global__ void edge_acc(const int* __restrict__ src, const int* __restrict__ dst,
                         const float* __restrict__ el, const float* __restrict__ er,
                         const unsigned* __restrict__ menc, float* __restrict__ sarr,
                         const float* __restrict__ Psrc, float* __restrict__ ft)
{
    int warp = (blockIdx.x * blockDim.x + threadIdx.x) >> 5;
    int lane = threadIdx.x & 31;
    if (warp >= EDG) return;
    int s = src[warp], d = dst[warp];
    float w = 0.f;
    if (lane < KH) {
        float v = leaky(el[s * KH + lane] + er[d * KH + lane]);
        float m = dec_f(menc[d * KH + lane]);
        w = __expf(v - m);
        atomicAdd(&sarr[d * KH + lane], w);
    }
#pragma unroll
    for (int k = 0; k < KH; k++) {
        float wk = __shfl_sync(0xffffffffu, w, k);
        float val = Psrc[(size_t)s * KD + k * DH + lane];
        atomicAdd(&ft[(size_t)d * KD + k * DH + lane], wk * val);
    }
}

// ---------------- normalize + relu (in place on ft) ----------------
__global__ void norm_relu(float* __restrict__ ft, const float* __restrict__ sarr, int N)
{
    int tid = blockIdx.x * blockDim.x + threadIdx.x;
    if (tid >= N * KD) return;
    int n = tid >> 8;
    int k = (tid >> 5) & 7;
    float sv = sarr[n * KH + k];
    float v = sv > 0.f ? ft[tid] / sv : 0.f;
    ft[tid] = v > 0.f ? v : 0.f;
}

// ---------------- final author: gated residual (residual already in out) ----------------
__global__ void final_author(const float* __restrict__ rf_wb,
                             const float* __restrict__ resw, float* __restrict__ out)
{
    int tid = blockIdx.x * blockDim.x + threadIdx.x;
    if (tid >= NA * KD) return;
    float g = 1.f / (1.f + __expf(-resw[0]));
    out[tid] = g * rf_wb[tid] + (1.f - g) * out[tid];
}

// ---------------- final paper: semantic attention over {writes, cites} + gated residual ----------------
__global__ void final_paper(const float* __restrict__ rfw, const float* __restrict__ rfc,
                            const float* __restrict__ nodep, const float* __restrict__ attnM,
                            const float* __restrict__ resw, float* __restrict__ out)
{
    int n = blockIdx.x;
    int k = threadIdx.x >> 5;
    int lane = threadIdx.x & 31;
    size_t idx = (size_t)n * KD + k * DH + lane;
    float np = nodep[idx], rw = rfw[idx], rc = rfc[idx];
    float a1 = attnM[k * 64 + lane];
    float a2 = attnM[k * 64 + 32 + lane];
    float sw = a1 * np + a2 * rw;
    float sc = a1 * np + a2 * rc;
#pragma unroll
    for (int s = 16; s > 0; s >>= 1) {
        sw += __shfl_xor_sync(0xffffffffu, sw, s);
        sc += __shfl_xor_sync(0xffffffffu, sc, s);
    }
    sw = leaky(sw);
    sc = leaky(sc);
    float mx = fmaxf(sw, sc);
    float ew = __expf(sw - mx), ec = __expf(sc - mx);
    float aw = ew / (ew + ec);
    float val = aw * rw + (1.f - aw) * rc;
    float g = 1.f / (1.f + __expf(-resw[0]));
    size_t o = (size_t)NA * KD + idx;
    out[o] = g * val + (1.f - g) * out[o];
}

// ---------------- launch ----------------
extern "C" void kernel_launch(void* const* d_in, const int* in_sizes, int n_in,
                              void* d_out, int out_size)
{
    const float* feats_author    = (const float*)d_in[0];
    const float* feats_paper     = (const float*)d_in[1];
    const float* W_micro_author  = (const float*)d_in[2];
    const float* W_micro_paper   = (const float*)d_in[3];
    const float* attn_micro_a    = (const float*)d_in[4];
    const float* attn_micro_p    = (const float*)d_in[5];
    const float* W_macro_node_a  = (const float*)d_in[6];  (void)W_macro_node_a;
    const float* W_macro_node_p  = (const float*)d_in[7];
    const float* W_rel_writes    = (const float*)d_in[8];
    const float* W_rel_wb        = (const float*)d_in[9];
    const float* W_rel_cites     = (const float*)d_in[10];
    const float* attn_macro      = (const float*)d_in[11];
    const float* W_res_author    = (const float*)d_in[12];
    const float* b_res_author    = (const float*)d_in[13];
    const float* W_res_paper     = (const float*)d_in[14];
    const float* b_res_paper     = (const float*)d_in[15];
    const float* res_w_author    = (const float*)d_in[16];
    const float* res_w_paper     = (const float*)d_in[17];
    const int*   writes_src      = (const int*)d_in[18];
    const int*   writes_dst      = (const int*)d_in[19];
    const int*   wb_src          = (const int*)d_in[20];
    const int*   wb_dst          = (const int*)d_in[21];
    const int*   cites_src       = (const int*)d_in[22];
    const int*   cites_dst       = (const int*)d_in[23];
    float* out = (float*)d_out;

    // resolve device scratch addresses
    float *PA, *PP, *elA_aA, *erP_aA, *elP_aP, *erA_aP, *erP_aP;
    unsigned *m_w, *m_wb, *m_c;
    float *s_w, *s_wb, *s_c, *ft_w, *ft_wb, *ft_c;
    float *rf_w, *rf_wb, *rf_c, *nodeP;
    cudaGetSymbolAddress((void**)&PA, g_PA);
    cudaGetSymbolAddress((void**)&PP, g_PP);
    cudaGetSymbolAddress((void**)&elA_aA, g_elA_aA);
    cudaGetSymbolAddress((void**)&erP_aA, g_erP_aA);
    cudaGetSymbolAddress((void**)&elP_aP, g_elP_aP);
    cudaGetSymbolAddress((void**)&erA_aP, g_erA_aP);
    cudaGetSymbolAddress((void**)&erP_aP, g_erP_aP);
    cudaGetSymbolAddress((void**)&m_w, g_m_w);
    cudaGetSymbolAddress((void**)&m_wb, g_m_wb);
    cudaGetSymbolAddress((void**)&m_c, g_m_c);
    cudaGetSymbolAddress((void**)&s_w, g_s_w);
    cudaGetSymbolAddress((void**)&s_wb, g_s_wb);
    cudaGetSymbolAddress((void**)&s_c, g_s_c);
    cudaGetSymbolAddress((void**)&ft_w, g_ft_w);
    cudaGetSymbolAddress((void**)&ft_wb, g_ft_wb);
    cudaGetSymbolAddress((void**)&ft_c, g_ft_c);
    cudaGetSymbolAddress((void**)&rf_w, g_rf_w);
    cudaGetSymbolAddress((void**)&rf_wb, g_rf_wb);
    cudaGetSymbolAddress((void**)&rf_c, g_rf_c);
    cudaGetSymbolAddress((void**)&nodeP, g_nodeP);

    dim3 ggrid((NA + 127) / 128, 2);

    // micro projections
    gemm128<<<ggrid, 256>>>(feats_author, W_micro_author, nullptr, PA, NA);
    gemm128<<<ggrid, 256>>>(feats_paper,  W_micro_paper,  nullptr, PP, NP);

    // attention dot products (5 combos needed)
    attn_dot<<<NA, 256>>>(PA, attn_micro_a, 0,  elA_aA);
    attn_dot<<<NP, 256>>>(PP, attn_micro_a, DH, erP_aA);
    attn_dot<<<NP, 256>>>(PP, attn_micro_p, 0,  elP_aP);
    attn_dot<<<NA, 256>>>(PA, attn_micro_p, DH, erA_aP);
    attn_dot<<<NP, 256>>>(PP, attn_micro_p, DH, erP_aP);

    // zero accumulators
    init_buffers<<<(NP * KD + 255) / 256, 256>>>();

    // edge softmax pass 1 (segment max)
    int ebl = (EDG + 255) / 256;
    edge_max<<<ebl, 256>>>(writes_src, writes_dst, elA_aA, erP_aA, m_w);
    edge_max<<<ebl, 256>>>(wb_src,     wb_dst,     elP_aP, erA_aP, m_wb);
    edge_max<<<ebl, 256>>>(cites_src,  cites_dst,  elP_aP, erP_aP, m_c);

    // edge softmax pass 2 (accumulate) — warp per edge
    int abl = (EDG * 32 + 255) / 256;
    edge_acc<<<abl, 256>>>(writes_src, writes_dst, elA_aA, erP_aA, m_w,  s_w,  PA, ft_w);
    edge_acc<<<abl, 256>>>(wb_src,     wb_dst,     elP_aP, erA_aP, m_wb, s_wb, PP, ft_wb);
    edge_acc<<<abl, 256>>>(cites_src,  cites_dst,  elP_aP, erP_aP, m_c,  s_c,  PP, ft_c);

    // normalize + relu (in place)
    int nbl = (NP * KD + 255) / 256;
    norm_relu<<<nbl, 256>>>(ft_w,  s_w,  NP);
    norm_relu<<<nbl, 256>>>(ft_wb, s_wb, NA);
    norm_relu<<<nbl, 256>>>(ft_c,  s_c,  NP);

    // macro projections
    gemm128<<<ggrid, 256>>>(ft_w,  W_rel_writes, nullptr, rf_w,  NP);
    gemm128<<<ggrid, 256>>>(ft_wb, W_rel_wb,     nullptr, rf_wb, NA);
    gemm128<<<ggrid, 256>>>(ft_c,  W_rel_cites,  nullptr, rf_c,  NP);
    gemm128<<<ggrid, 256>>>(feats_paper, W_macro_node_p, nullptr, nodeP, NP);

    // residual projections directly into output halves
    gemm128<<<ggrid, 256>>>(feats_author, W_res_author, b_res_author, out, NA);
    gemm128<<<ggrid, 256>>>(feats_paper,  W_res_paper,  b_res_paper,  out + (size_t)NA * KD, NP);

    // final fusion
    final_author<<<(NA * KD + 255) / 256, 256>>>(rf_wb, res_w_author, out);
    final_paper<<<NP, 256>>>(rf_w, rf_c, nodeP, attn_macro, res_w_paper, out);
}

// round 3
// speedup vs baseline: 1.5979x; 1.5979x over previous
#include <cuda_runtime.h>
#include <cstdint>
#include <math.h>

// ---------------- problem constants ----------------
#define NA 50000
#define NP 50000
#define EDG 400000
#define KH 8
#define DH 32
#define KD 256
#define SLOPE 0.2f

// GEMM tiling
#define BM 128
#define BN 128
#define BK 16
#define NKT (KD / BK)      // 16
#define LDA 132            // padded smem stride
#define LDB 132

// ---------------- device scratch ----------------
__device__ float g_PA[NA * KD];
__device__ float g_PP[NP * KD];

__device__ float g_elA_aA[NA * KH];
__device__ float g_erP_aA[NP * KH];
__device__ float g_elP_aP[NP * KH];
__device__ float g_erA_aP[NA * KH];
__device__ float g_erP_aP[NP * KH];

__device__ unsigned g_m_w[NP * KH];
__device__ unsigned g_m_wb[NA * KH];
__device__ unsigned g_m_c[NP * KH];
__device__ float    g_s_w[NP * KH];
__device__ float    g_s_wb[NA * KH];
__device__ float    g_s_c[NP * KH];
__device__ float    g_ft_w[NP * KD];
__device__ float    g_ft_wb[NA * KD];
__device__ float    g_ft_c[NP * KD];

__device__ float g_rf_w[NP * KD];
__device__ float g_rf_wb[NA * KD];
__device__ float g_rf_c[NP * KD];
__device__ float g_nodeP[NP * KD];

// ---------------- helpers ----------------
__device__ __forceinline__ unsigned enc_f(float f) {
    unsigned u = __float_as_uint(f);
    return u ^ ((unsigned)((int)u >> 31) | 0x80000000u);
}
__device__ __forceinline__ float dec_f(unsigned u) {
    return (u & 0x80000000u) ? __uint_as_float(u ^ 0x80000000u)
                             : __uint_as_float(~u);
}
__device__ __forceinline__ float leaky(float v) {
    return v > 0.f ? v : SLOPE * v;
}
__device__ __forceinline__ uint32_t f2tf32(float f) {
    uint32_t r;
    asm("cvt.rna.tf32.f32 %0, %1;" : "=r"(r) : "f"(f));
    return r;
}
__device__ __forceinline__ void mma_tf32(float c[4], uint32_t a0, uint32_t a1,
                                         uint32_t a2, uint32_t a3,
                                         uint32_t b0, uint32_t b1) {
    asm volatile(
        "mma.sync.aligned.m16n8k8.row.col.f32.tf32.tf32.f32 "
        "{%0,%1,%2,%3}, {%4,%5,%6,%7}, {%8,%9}, {%0,%1,%2,%3};"
        : "+f"(c[0]), "+f"(c[1]), "+f"(c[2]), "+f"(c[3])
        : "r"(a0), "r"(a1), "r"(a2), "r"(a3), "r"(b0), "r"(b1));
}

// ---------------- tf32 tensor-core GEMM: C[M,256] = A[M,256] @ B[256,256] (+bias) ----------------
// 128x128 tile, BK=16, 256 threads (8 warps: 4 in M x 2 in N), warp tile 32x64.
__global__ void __launch_bounds__(256) gemm_mma(
    const float* __restrict__ A, const float* __restrict__ B,
    const float* __restrict__ bias, float* __restrict__ C, int M)
{
    __shared__ uint32_t As[2][BK][LDA];   // [k][m], tf32 bits
    __shared__ uint32_t Bs[2][BK][LDB];   // [k][n], tf32 bits

    const int tid = threadIdx.x;
    const int lane = tid & 31;
    const int wid = tid >> 5;
    const int wm = (wid & 3) * 32;        // warp m offset
    const int wn = (wid >> 2) * 64;       // warp n offset
    const int m0 = blockIdx.x * BM;
    const int n0 = blockIdx.y * BN;

    const int qr = lane >> 2;             // 0..7
    const int qc = lane & 3;              // 0..3

    float acc[2][8][4];
#pragma unroll
    for (int mi = 0; mi < 2; mi++)
#pragma unroll
        for (int ni = 0; ni < 8; ni++)
#pragma unroll
            for (int r = 0; r < 4; r++) acc[mi][ni][r] = 0.f;

    // global load indices
    const int am = tid >> 1;                  // 0..127
    const int aq = (tid & 1) * 8;             // k offset 0 or 8
    const int bk = tid >> 4;                  // 0..15
    const int bn = (tid & 15) * 8;            // 0..120

    // prefetch regs
    float4 rA[2], rB[2];

    auto g_load = [&](int kt) {
        const int k0 = kt * BK;
        int row = m0 + am;
        if (row < M) {
            rA[0] = *(const float4*)&A[(size_t)row * KD + k0 + aq];
            rA[1] = *(const float4*)&A[(size_t)row * KD + k0 + aq + 4];
        } else {
            rA[0] = make_float4(0.f, 0.f, 0.f, 0.f);
            rA[1] = rA[0];
        }
        rB[0] = *(const float4*)&B[(size_t)(k0 + bk) * KD + n0 + bn];
        rB[1] = *(const float4*)&B[(size_t)(k0 + bk) * KD + n0 + bn + 4];
    };
    auto s_store = [&](int buf) {
        As[buf][aq + 0][am] = f2tf32(rA[0].x);
        As[buf][aq + 1][am] = f2tf32(rA[0].y);
        As[buf][aq + 2][am] = f2tf32(rA[0].z);
        As[buf][aq + 3][am] = f2tf32(rA[0].w);
        As[buf][aq + 4][am] = f2tf32(rA[1].x);
        As[buf][aq + 5][am] = f2tf32(rA[1].y);
        As[buf][aq + 6][am] = f2tf32(rA[1].z);
        As[buf][aq + 7][am] = f2tf32(rA[1].w);
        Bs[buf][bk][bn + 0] = f2tf32(rB[0].x);
        Bs[buf][bk][bn + 1] = f2tf32(rB[0].y);
        Bs[buf][bk][bn + 2] = f2tf32(rB[0].z);
        Bs[buf][bk][bn + 3] = f2tf32(rB[0].w);
        Bs[buf][bk][bn + 4] = f2tf32(rB[1].x);
        Bs[buf][bk][bn + 5] = f2tf32(rB[1].y);
        Bs[buf][bk][bn + 6] = f2tf32(rB[1].z);
        Bs[buf][bk][bn + 7] = f2tf32(rB[1].w);
    };

    g_load(0);
    s_store(0);
    __syncthreads();

    for (int kt = 0; kt < NKT; kt++) {
        const int cur = kt & 1;
        if (kt + 1 < NKT) g_load(kt + 1);

#pragma unroll
        for (int ks = 0; ks < BK; ks += 8) {
            uint32_t a[2][4], b[8][2];
#pragma unroll
            for (int mi = 0; mi < 2; mi++) {
                int mb = wm + mi * 16;
                a[mi][0] = As[cur][ks + qc][mb + qr];
                a[mi][1] = As[cur][ks + qc][mb + qr + 8];
                a[mi][2] = As[cur][ks + qc + 4][mb + qr];
                a[mi][3] = As[cur][ks + qc + 4][mb + qr + 8];
            }
#pragma unroll
            for (int ni = 0; ni < 8; ni++) {
                int nb = wn + ni * 8;
                b[ni][0] = Bs[cur][ks + qc][nb + qr];
                b[ni][1] = Bs[cur][ks + qc + 4][nb + qr];
            }
#pragma unroll
            for (int mi = 0; mi < 2; mi++)
#pragma unroll
                for (int ni = 0; ni < 8; ni++)
                    mma_tf32(acc[mi][ni], a[mi][0], a[mi][1], a[mi][2], a[mi][3],
                             b[ni][0], b[ni][1]);
        }

        if (kt + 1 < NKT) {
            s_store(1 - cur);
            __syncthreads();
        }
    }

    // epilogue
#pragma unroll
    for (int mi = 0; mi < 2; mi++) {
#pragma unroll
        for (int half = 0; half < 2; half++) {
            int row = m0 + wm + mi * 16 + qr + half * 8;
            if (row >= M) continue;
            float* dst = &C[(size_t)row * KD + n0 + wn];
#pragma unroll
            for (int ni = 0; ni < 8; ni++) {
                int col = ni * 8 + qc * 2;
                float2 v;
                v.x = acc[mi][ni][half * 2 + 0];
                v.y = acc[mi][ni][half * 2 + 1];
                if (bias) {
                    v.x += bias[n0 + wn + col + 0];
                    v.y += bias[n0 + wn + col + 1];
                }
                *(float2*)&dst[col] = v;
            }
        }
    }
}

// ---------------- fused attention dots ----------------
__global__ void attn_dots_author(const float* __restrict__ P,
                                 const float* __restrict__ attn_a,
                                 const float* __restrict__ attn_p,
                                 float* __restrict__ el_aA, float* __restrict__ er_aP)
{
    int n = blockIdx.x, k = threadIdx.x >> 5, lane = threadIdx.x & 31;
    float p = P[(size_t)n * KD + k * DH + lane];
    float v1 = p * attn_a[k * 64 + lane];
    float v2 = p * attn_p[k * 64 + 32 + lane];
#pragma unroll
    for (int s = 16; s > 0; s >>= 1) {
        v1 += __shfl_xor_sync(0xffffffffu, v1, s);
        v2 += __shfl_xor_sync(0xffffffffu, v2, s);
    }
    if (lane == 0) { el_aA[n * KH + k] = v1; er_aP[n * KH + k] = v2; }
}

__global__ void attn_dots_paper(const float* __restrict__ P,
                                const float* __restrict__ attn_a,
                                const float* __restrict__ attn_p,
                                float* __restrict__ er_aA, float* __restrict__ el_aP,
                                float* __restrict__ er_aP)
{
    int n = blockIdx.x, k = threadIdx.x >> 5, lane = threadIdx.x & 31;
    float p = P[(size_t)n * KD + k * DH + lane];
    float v1 = p * attn_a[k * 64 + 32 + lane];
    float v2 = p * attn_p[k * 64 + lane];
    float v3 = p * attn_p[k * 64 + 32 + lane];
#pragma unroll
    for (int s = 16; s > 0; s >>= 1) {
        v1 += __shfl_xor_sync(0xffffffffu, v1, s);
        v2 += __shfl_xor_sync(0xffffffffu, v2, s);
        v3 += __shfl_xor_sync(0xffffffffu, v3, s);
    }
    if (lane == 0) {
        er_aA[n * KH + k] = v1;
        el_aP[n * KH + k] = v2;
        er_aP[n * KH + k] = v3;
    }
}

// ---------------- init buffers ----------------
__global__ void init_buffers()
{
    int tid = blockIdx.x * blockDim.x + threadIdx.x;
    if (tid < NP * KD) { g_ft_w[tid] = 0.f; g_ft_c[tid] = 0.f; }
    if (tid < NA * KD) { g_ft_wb[tid] = 0.f; }
    if (tid < NP * KH) { g_m_w[tid] = 0u; g_m_c[tid] = 0u; g_s_w[tid] = 0.f; g_s_c[tid] = 0.f; }
    if (tid < NA * KH) { g_m_wb[tid] = 0u; g_s_wb[tid] = 0.f; }
}

// ---------------- edge pass 1: segment max ----------------
__global__ void edge_max(const int* __restrict__ src, const int* __restrict__ dst,
                         const float* __restrict__ el, const float* __restrict__ er,
                         unsigned* __restrict__ menc)
{
    int e = blockIdx.x * blockDim.x + threadIdx.x;
    if (e >= EDG) return;
    int s = src[e], d = dst[e];
    float4 l0 = *(const float4*)&el[s * KH];
    float4 l1 = *(const float4*)&el[s * KH + 4];
    float4 r0 = *(const float4*)&er[d * KH];
    float4 r1 = *(const float4*)&er[d * KH + 4];
    float vs[8] = { l0.x + r0.x, l0.y + r0.y, l0.z + r0.z, l0.w + r0.w,
                    l1.x + r1.x, l1.y + r1.y, l1.z + r1.z, l1.w + r1.w };
#pragma unroll
    for (int k = 0; k < 8; k++)
        atomicMax(&menc[d * KH + k], enc_f(leaky(vs[k])));
}

// ---------------- edge pass 2: accumulate ----------------
__global__ void edge_acc(const int* __restrict__ src, const int* __restrict__ dst,
                         const float* __restrict__ el, const float* __restrict__ er,
                         const unsigned* __restrict__ menc, float* __restrict__ sarr,
                         const float* __restrict__ Psrc, float* __restrict__ ft)
{
    int warp = (blockIdx.x * blockDim.x + threadIdx.x) >> 5;
    int lane = threadIdx.x & 31;
    if (warp >= EDG) return;
    int s = src[warp], d = dst[warp];
    float w = 0.f;
    if (lane < KH) {
        float v = leaky(el[s * KH + lane] + er[d * KH + lane]);
        float m = dec_f(menc[d * KH + lane]);
        w = __expf(v - m);
        atomicAdd(&sarr[d * KH + lane], w);
    }
#pragma unroll
    for (int k = 0; k < KH; k++) {
        float wk = __shfl_sync(0xffffffffu, w, k);
        float val = Psrc[(size_t)s * KD + k * DH + lane];
        atomicAdd(&ft[(size_t)d * KD + k * DH + lane], wk * val);
    }
}

// ---------------- normalize + relu ----------------
__global__ void norm_relu(float* __restrict__ ft, const float* __restrict__ sarr, int N)
{
    int tid = blockIdx.x * blockDim.x + threadIdx.x;
    if (tid >= N * KD) return;
    int n = tid >> 8;
    int k = (tid >> 5) & 7;
    float sv = sarr[n * KH + k];
    float v = sv > 0.f ? ft[tid] / sv : 0.f;
    ft[tid] = v > 0.f ? v : 0.f;
}

// ---------------- final author ----------------
__global__ void final_author(const float* __restrict__ rf_wb,
                             const float* __restrict__ resw, float* __restrict__ out)
{
    int tid = blockIdx.x * blockDim.x + threadIdx.x;
    if (tid >= NA * KD) return;
    float g = 1.f / (1.f + __expf(-resw[0]));
    out[tid] = g * rf_wb[tid] + (1.f - g) * out[tid];
}

// ---------------- final paper ----------------
__global__ void final_paper(const float* __restrict__ rfw, const float* __restrict__ rfc,
                            const float* __restrict__ nodep, const float* __restrict__ attnM,
                            const float* __restrict__ resw, float* __restrict__ out)
{
    int n = blockIdx.x;
    int k = threadIdx.x >> 5;
    int lane = threadIdx.x & 31;
    size_t idx = (size_t)n * KD + k * DH + lane;
    float np = nodep[idx], rw = rfw[idx], rc = rfc[idx];
    float a1 = attnM[k * 64 + lane];
    float a2 = attnM[k * 64 + 32 + lane];
    float sw = a1 * np + a2 * rw;
    float sc = a1 * np + a2 * rc;
#pragma unroll
    for (int s = 16; s > 0; s >>= 1) {
        sw += __shfl_xor_sync(0xffffffffu, sw, s);
        sc += __shfl_xor_sync(0xffffffffu, sc, s);
    }
    sw = leaky(sw);
    sc = leaky(sc);
    float mx = fmaxf(sw, sc);
    float ew = __expf(sw - mx), ec = __expf(sc - mx);
    float aw = ew / (ew + ec);
    float val = aw * rw + (1.f - aw) * rc;
    float g = 1.f / (1.f + __expf(-resw[0]));
    size_t o = (size_t)NA * KD + idx;
    out[o] = g * val + (1.f - g) * out[o];
}

// ---------------- launch ----------------
extern "C" void kernel_launch(void* const* d_in, const int* in_sizes, int n_in,
                              void* d_out, int out_size)
{
    const float* feats_author    = (const float*)d_in[0];
    const float* feats_paper     = (const float*)d_in[1];
    const float* W_micro_author  = (const float*)d_in[2];
    const float* W_micro_paper   = (const float*)d_in[3];
    const float* attn_micro_a    = (const float*)d_in[4];
    const float* attn_micro_p    = (const float*)d_in[5];
    const float* W_macro_node_p  = (const float*)d_in[7];
    const float* W_rel_writes    = (const float*)d_in[8];
    const float* W_rel_wb        = (const float*)d_in[9];
    const float* W_rel_cites     = (const float*)d_in[10];
    const float* attn_macro      = (const float*)d_in[11];
    const float* W_res_author    = (const float*)d_in[12];
    const float* b_res_author    = (const float*)d_in[13];
    const float* W_res_paper     = (const float*)d_in[14];
    const float* b_res_paper     = (const float*)d_in[15];
    const float* res_w_author    = (const float*)d_in[16];
    const float* res_w_paper     = (const float*)d_in[17];
    const int*   writes_src      = (const int*)d_in[18];
    const int*   writes_dst      = (const int*)d_in[19];
    const int*   wb_src          = (const int*)d_in[20];
    const int*   wb_dst          = (const int*)d_in[21];
    const int*   cites_src       = (const int*)d_in[22];
    const int*   cites_dst       = (const int*)d_in[23];
    float* out = (float*)d_out;

    float *PA, *PP, *elA_aA, *erP_aA, *elP_aP, *erA_aP, *erP_aP;
    unsigned *m_w, *m_wb, *m_c;
    float *s_w, *s_wb, *s_c, *ft_w, *ft_wb, *ft_c;
    float *rf_w, *rf_wb, *rf_c, *nodeP;
    cudaGetSymbolAddress((void**)&PA, g_PA);
    cudaGetSymbolAddress((void**)&PP, g_PP);
    cudaGetSymbolAddress((void**)&elA_aA, g_elA_aA);
    cudaGetSymbolAddress((void**)&erP_aA, g_erP_aA);
    cudaGetSymbolAddress((void**)&elP_aP, g_elP_aP);
    cudaGetSymbolAddress((void**)&erA_aP, g_erA_aP);
    cudaGetSymbolAddress((void**)&erP_aP, g_erP_aP);
    cudaGetSymbolAddress((void**)&m_w, g_m_w);
    cudaGetSymbolAddress((void**)&m_wb, g_m_wb);
    cudaGetSymbolAddress((void**)&m_c, g_m_c);
    cudaGetSymbolAddress((void**)&s_w, g_s_w);
    cudaGetSymbolAddress((void**)&s_wb, g_s_wb);
    cudaGetSymbolAddress((void**)&s_c, g_s_c);
    cudaGetSymbolAddress((void**)&ft_w, g_ft_w);
    cudaGetSymbolAddress((void**)&ft_wb, g_ft_wb);
    cudaGetSymbolAddress((void**)&ft_c, g_ft_c);
    cudaGetSymbolAddress((void**)&rf_w, g_rf_w);
    cudaGetSymbolAddress((void**)&rf_wb, g_rf_wb);
    cudaGetSymbolAddress((void**)&rf_c, g_rf_c);
    cudaGetSymbolAddress((void**)&nodeP, g_nodeP);

    dim3 ggrid((NA + BM - 1) / BM, KD / BN);   // (391, 2)

    // micro projections (tf32 mma)
    gemm_mma<<<ggrid, 256>>>(feats_author, W_micro_author, nullptr, PA, NA);
    gemm_mma<<<ggrid, 256>>>(feats_paper,  W_micro_paper,  nullptr, PP, NP);

    // fused attention dots
    attn_dots_author<<<NA, 256>>>(PA, attn_micro_a, attn_micro_p, elA_aA, erA_aP);
    attn_dots_paper <<<NP, 256>>>(PP, attn_micro_a, attn_micro_p, erP_aA, elP_aP, erP_aP);

    // zero accumulators
    init_buffers<<<(NP * KD + 255) / 256, 256>>>();

    // edge softmax pass 1
    int ebl = (EDG + 255) / 256;
    edge_max<<<ebl, 256>>>(writes_src, writes_dst, elA_aA, erP_aA, m_w);
    edge_max<<<ebl, 256>>>(wb_src,     wb_dst,     elP_aP, erA_aP, m_wb);
    edge_max<<<ebl, 256>>>(cites_src,  cites_dst,  elP_aP, erP_aP, m_c);

    // edge softmax pass 2
    int abl = (EDG * 32 + 255) / 256;
    edge_acc<<<abl, 256>>>(writes_src, writes_dst, elA_aA, erP_aA, m_w,  s_w,  PA, ft_w);
    edge_acc<<<abl, 256>>>(wb_src,     wb_dst,     elP_aP, erA_aP, m_wb, s_wb, PP, ft_wb);
    edge_acc<<<abl, 256>>>(cites_src,  cites_dst,  elP_aP, erP_aP, m_c,  s_c,  PP, ft_c);

    // normalize + relu
    int nbl = (NP * KD + 255) / 256;
    norm_relu<<<nbl, 256>>>(ft_w,  s_w,  NP);
    norm_relu<<<nbl, 256>>>(ft_wb, s_wb, NA);
    norm_relu<<<nbl, 256>>>(ft_c,  s_c,  NP);

    // macro projections (tf32 mma)
    gemm_mma<<<ggrid, 256>>>(ft_w,  W_rel_writes,  nullptr, rf_w,  NP);
    gemm_mma<<<ggrid, 256>>>(ft_wb, W_rel_wb,      nullptr, rf_wb, NA);
    gemm_mma<<<ggrid, 256>>>(ft_c,  W_rel_cites,   nullptr, rf_c,  NP);
    gemm_mma<<<ggrid, 256>>>(feats_paper, W_macro_node_p, nullptr, nodeP, NP);

    // residual projections into output halves
    gemm_mma<<<ggrid, 256>>>(feats_author, W_res_author, b_res_author, out, NA);
    gemm_mma<<<ggrid, 256>>>(feats_paper,  W_res_paper,  b_res_paper,
                             out + (size_t)NA * KD, NP);

    // final fusion
    final_author<<<(NA * KD + 255) / 256, 256>>>(rf_wb, res_w_author, out);
    final_paper<<<NP, 256>>>(rf_w, rf_c, nodeP, attn_macro, res_w_paper, out);
}

// round 4
// speedup vs baseline: 1.7180x; 1.0752x over previous
#include <cuda_runtime.h>
#include <cstdint>
#include <math.h>

// ---------------- problem constants ----------------
#define NA 50000
#define NP 50000
#define EDG 400000
#define KH 8
#define DH 32
#define KD 256
#define SLOPE 0.2f

// GEMM tiling
#define BM 128
#define BN 128
#define BK 16
#define NKT (KD / BK)      // 16
#define LDA 132
#define LDB 132

// ---------------- device scratch ----------------
__device__ float g_PA[NA * KD];
__device__ float g_PP[NP * KD];

__device__ float g_elA_aA[NA * KH];
__device__ float g_erP_aA[NP * KH];
__device__ float g_elP_aP[NP * KH];
__device__ float g_erA_aP[NA * KH];
__device__ float g_erP_aP[NP * KH];

__device__ float g_ft_w[NP * KD];
__device__ float g_ft_wb[NA * KD];
__device__ float g_ft_c[NP * KD];

__device__ float g_rf_w[NP * KD];
__device__ float g_rf_wb[NA * KD];
__device__ float g_rf_c[NP * KD];
__device__ float g_nodeP[NP * KD];

// CSR scratch (reused serially across the 3 relations)
__device__ int g_counts[50001];
__device__ int g_cursor[50000];
__device__ int g_offsets[50001];
__device__ int g_ssort[EDG];     // src ids sorted by dst

// ---------------- helpers ----------------
__device__ __forceinline__ float leaky(float v) {
    return v > 0.f ? v : SLOPE * v;
}
__device__ __forceinline__ uint32_t f2tf32(float f) {
    uint32_t r;
    asm("cvt.rna.tf32.f32 %0, %1;" : "=r"(r) : "f"(f));
    return r;
}
__device__ __forceinline__ void mma_tf32(float c[4], uint32_t a0, uint32_t a1,
                                         uint32_t a2, uint32_t a3,
                                         uint32_t b0, uint32_t b1) {
    asm volatile(
        "mma.sync.aligned.m16n8k8.row.col.f32.tf32.tf32.f32 "
        "{%0,%1,%2,%3}, {%4,%5,%6,%7}, {%8,%9}, {%0,%1,%2,%3};"
        : "+f"(c[0]), "+f"(c[1]), "+f"(c[2]), "+f"(c[3])
        : "r"(a0), "r"(a1), "r"(a2), "r"(a3), "r"(b0), "r"(b1));
}

// ---------------- tf32 tensor-core GEMM (unchanged from R3) ----------------
__global__ void __launch_bounds__(256) gemm_mma(
    const float* __restrict__ A, const float* __restrict__ B,
    const float* __restrict__ bias, float* __restrict__ C, int M)
{
    __shared__ uint32_t As[2][BK][LDA];
    __shared__ uint32_t Bs[2][BK][LDB];

    const int tid = threadIdx.x;
    const int lane = tid & 31;
    const int wid = tid >> 5;
    const int wm = (wid & 3) * 32;
    const int wn = (wid >> 2) * 64;
    const int m0 = blockIdx.x * BM;
    const int n0 = blockIdx.y * BN;

    const int qr = lane >> 2;
    const int qc = lane & 3;

    float acc[2][8][4];
#pragma unroll
    for (int mi = 0; mi < 2; mi++)
#pragma unroll
        for (int ni = 0; ni < 8; ni++)
#pragma unroll
            for (int r = 0; r < 4; r++) acc[mi][ni][r] = 0.f;

    const int am = tid >> 1;
    const int aq = (tid & 1) * 8;
    const int bk = tid >> 4;
    const int bn = (tid & 15) * 8;

    float4 rA[2], rB[2];

    auto g_load = [&](int kt) {
        const int k0 = kt * BK;
        int row = m0 + am;
        if (row < M) {
            rA[0] = *(const float4*)&A[(size_t)row * KD + k0 + aq];
            rA[1] = *(const float4*)&A[(size_t)row * KD + k0 + aq + 4];
        } else {
            rA[0] = make_float4(0.f, 0.f, 0.f, 0.f);
            rA[1] = rA[0];
        }
        rB[0] = *(const float4*)&B[(size_t)(k0 + bk) * KD + n0 + bn];
        rB[1] = *(const float4*)&B[(size_t)(k0 + bk) * KD + n0 + bn + 4];
    };
    auto s_store = [&](int buf) {
        As[buf][aq + 0][am] = f2tf32(rA[0].x);
        As[buf][aq + 1][am] = f2tf32(rA[0].y);
        As[buf][aq + 2][am] = f2tf32(rA[0].z);
        As[buf][aq + 3][am] = f2tf32(rA[0].w);
        As[buf][aq + 4][am] = f2tf32(rA[1].x);
        As[buf][aq + 5][am] = f2tf32(rA[1].y);
        As[buf][aq + 6][am] = f2tf32(rA[1].z);
        As[buf][aq + 7][am] = f2tf32(rA[1].w);
        Bs[buf][bk][bn + 0] = f2tf32(rB[0].x);
        Bs[buf][bk][bn + 1] = f2tf32(rB[0].y);
        Bs[buf][bk][bn + 2] = f2tf32(rB[0].z);
        Bs[buf][bk][bn + 3] = f2tf32(rB[0].w);
        Bs[buf][bk][bn + 4] = f2tf32(rB[1].x);
        Bs[buf][bk][bn + 5] = f2tf32(rB[1].y);
        Bs[buf][bk][bn + 6] = f2tf32(rB[1].z);
        Bs[buf][bk][bn + 7] = f2tf32(rB[1].w);
    };

    g_load(0);
    s_store(0);
    __syncthreads();

    for (int kt = 0; kt < NKT; kt++) {
        const int cur = kt & 1;
        if (kt + 1 < NKT) g_load(kt + 1);

#pragma unroll
        for (int ks = 0; ks < BK; ks += 8) {
            uint32_t a[2][4], b[8][2];
#pragma unroll
            for (int mi = 0; mi < 2; mi++) {
                int mb = wm + mi * 16;
                a[mi][0] = As[cur][ks + qc][mb + qr];
                a[mi][1] = As[cur][ks + qc][mb + qr + 8];
                a[mi][2] = As[cur][ks + qc + 4][mb + qr];
                a[mi][3] = As[cur][ks + qc + 4][mb + qr + 8];
            }
#pragma unroll
            for (int ni = 0; ni < 8; ni++) {
                int nb = wn + ni * 8;
                b[ni][0] = Bs[cur][ks + qc][nb + qr];
                b[ni][1] = Bs[cur][ks + qc + 4][nb + qr];
            }
#pragma unroll
            for (int mi = 0; mi < 2; mi++)
#pragma unroll
                for (int ni = 0; ni < 8; ni++)
                    mma_tf32(acc[mi][ni], a[mi][0], a[mi][1], a[mi][2], a[mi][3],
                             b[ni][0], b[ni][1]);
        }

        if (kt + 1 < NKT) {
            s_store(1 - cur);
            __syncthreads();
        }
    }

#pragma unroll
    for (int mi = 0; mi < 2; mi++) {
#pragma unroll
        for (int half = 0; half < 2; half++) {
            int row = m0 + wm + mi * 16 + qr + half * 8;
            if (row >= M) continue;
            float* dst = &C[(size_t)row * KD + n0 + wn];
#pragma unroll
            for (int ni = 0; ni < 8; ni++) {
                int col = ni * 8 + qc * 2;
                float2 v;
                v.x = acc[mi][ni][half * 2 + 0];
                v.y = acc[mi][ni][half * 2 + 1];
                if (bias) {
                    v.x += bias[n0 + wn + col + 0];
                    v.y += bias[n0 + wn + col + 1];
                }
                *(float2*)&dst[col] = v;
            }
        }
    }
}

// ---------------- fused attention dots ----------------
__global__ void attn_dots_author(const float* __restrict__ P,
                                 const float* __restrict__ attn_a,
                                 const float* __restrict__ attn_p,
                                 float* __restrict__ el_aA, float* __restrict__ er_aP)
{
    int n = blockIdx.x, k = threadIdx.x >> 5, lane = threadIdx.x & 31;
    float p = P[(size_t)n * KD + k * DH + lane];
    float v1 = p * attn_a[k * 64 + lane];
    float v2 = p * attn_p[k * 64 + 32 + lane];
#pragma unroll
    for (int s = 16; s > 0; s >>= 1) {
        v1 += __shfl_xor_sync(0xffffffffu, v1, s);
        v2 += __shfl_xor_sync(0xffffffffu, v2, s);
    }
    if (lane == 0) { el_aA[n * KH + k] = v1; er_aP[n * KH + k] = v2; }
}

__global__ void attn_dots_paper(const float* __restrict__ P,
                                const float* __restrict__ attn_a,
                                const float* __restrict__ attn_p,
                                float* __restrict__ er_aA, float* __restrict__ el_aP,
                                float* __restrict__ er_aP)
{
    int n = blockIdx.x, k = threadIdx.x >> 5, lane = threadIdx.x & 31;
    float p = P[(size_t)n * KD + k * DH + lane];
    float v1 = p * attn_a[k * 64 + 32 + lane];
    float v2 = p * attn_p[k * 64 + lane];
    float v3 = p * attn_p[k * 64 + 32 + lane];
#pragma unroll
    for (int s = 16; s > 0; s >>= 1) {
        v1 += __shfl_xor_sync(0xffffffffu, v1, s);
        v2 += __shfl_xor_sync(0xffffffffu, v2, s);
        v3 += __shfl_xor_sync(0xffffffffu, v3, s);
    }
    if (lane == 0) {
        er_aA[n * KH + k] = v1;
        el_aP[n * KH + k] = v2;
        er_aP[n * KH + k] = v3;
    }
}

// ---------------- CSR build ----------------
__global__ void csr_zero(int* __restrict__ counts, int* __restrict__ cursor, int n)
{
    int i = blockIdx.x * blockDim.x + threadIdx.x;
    if (i <= n) counts[i] = 0;
    if (i < n) cursor[i] = 0;
}

__global__ void csr_hist(const int* __restrict__ dst, int* __restrict__ counts)
{
    int e = blockIdx.x * blockDim.x + threadIdx.x;
    if (e < EDG) atomicAdd(&counts[dst[e]], 1);
}

// single-block exclusive scan over n elements; offsets[n] = total
__global__ void __launch_bounds__(1024) csr_scan(const int* __restrict__ counts,
                                                 int* __restrict__ offsets, int n)
{
    __shared__ int tmp[1024];
    __shared__ int carry;
    if (threadIdx.x == 0) carry = 0;
    __syncthreads();
    for (int base = 0; base < n; base += 1024) {
        int i = base + threadIdx.x;
        int v = (i < n) ? counts[i] : 0;
        tmp[threadIdx.x] = v;
        __syncthreads();
#pragma unroll
        for (int off = 1; off < 1024; off <<= 1) {
            int t = (threadIdx.x >= off) ? tmp[threadIdx.x - off] : 0;
            __syncthreads();
            tmp[threadIdx.x] += t;
            __syncthreads();
        }
        if (i < n) offsets[i] = carry + tmp[threadIdx.x] - v;
        __syncthreads();
        if (threadIdx.x == 1023) carry += tmp[1023];
        __syncthreads();
    }
    if (threadIdx.x == 0) offsets[n] = carry;
}

// scatter src ids into dst-sorted order
__global__ void csr_scatter(const int* __restrict__ src, const int* __restrict__ dst,
                            const int* __restrict__ offsets, int* __restrict__ cursor,
                            int* __restrict__ ssort)
{
    int e = blockIdx.x * blockDim.x + threadIdx.x;
    if (e >= EDG) return;
    int d = dst[e];
    int pos = offsets[d] + atomicAdd(&cursor[d], 1);
    ssort[pos] = src[e];
}

// ---------------- fused micro gather: softmax + weighted sum + relu, warp per dst ----------------
__global__ void micro_gather(const int* __restrict__ ssort, const int* __restrict__ offsets,
                             const float* __restrict__ el, const float* __restrict__ er,
                             const float* __restrict__ Psrc, float* __restrict__ ft, int n_dst)
{
    int d = (blockIdx.x * blockDim.x + threadIdx.x) >> 5;
    int lane = threadIdx.x & 31;
    if (d >= n_dst) return;
    int beg = offsets[d], end = offsets[d + 1];
    float* dstp = &ft[(size_t)d * KD + lane * 8];
    if (beg == end) {
        float4 z = make_float4(0.f, 0.f, 0.f, 0.f);
        *(float4*)dstp = z;
        *(float4*)(dstp + 4) = z;
        return;
    }
    float erv = (lane < KH) ? er[d * KH + lane] : 0.f;

    // pass 1: per-head max
    float mx = -1e30f;
    for (int i = beg; i < end; i++) {
        int s = ssort[i];
        if (lane < KH) mx = fmaxf(mx, leaky(el[s * KH + lane] + erv));
    }

    // pass 2: exp weights, sum, weighted feature accumulation
    const int hk = lane >> 2;   // head owning this lane's 8 columns
    float acc[8] = {0.f, 0.f, 0.f, 0.f, 0.f, 0.f, 0.f, 0.f};
    float se = 0.f;
    for (int i = beg; i < end; i++) {
        int s = ssort[i];
        float w = 0.f;
        if (lane < KH) {
            w = __expf(leaky(el[s * KH + lane] + erv) - mx);
            se += w;
        }
        float wk = __shfl_sync(0xffffffffu, w, hk);
        const float4* p = (const float4*)&Psrc[(size_t)s * KD + lane * 8];
        float4 p0 = p[0], p1 = p[1];
        acc[0] = fmaf(wk, p0.x, acc[0]);
        acc[1] = fmaf(wk, p0.y, acc[1]);
        acc[2] = fmaf(wk, p0.z, acc[2]);
        acc[3] = fmaf(wk, p0.w, acc[3]);
        acc[4] = fmaf(wk, p1.x, acc[4]);
        acc[5] = fmaf(wk, p1.y, acc[5]);
        acc[6] = fmaf(wk, p1.z, acc[6]);
        acc[7] = fmaf(wk, p1.w, acc[7]);
    }
    float inv = 1.f / __shfl_sync(0xffffffffu, se, hk);
    float4 o0, o1;
    o0.x = fmaxf(acc[0] * inv, 0.f);
    o0.y = fmaxf(acc[1] * inv, 0.f);
    o0.z = fmaxf(acc[2] * inv, 0.f);
    o0.w = fmaxf(acc[3] * inv, 0.f);
    o1.x = fmaxf(acc[4] * inv, 0.f);
    o1.y = fmaxf(acc[5] * inv, 0.f);
    o1.z = fmaxf(acc[6] * inv, 0.f);
    o1.w = fmaxf(acc[7] * inv, 0.f);
    *(float4*)dstp = o0;
    *(float4*)(dstp + 4) = o1;
}

// ---------------- final author ----------------
__global__ void final_author(const float* __restrict__ rf_wb,
                             const float* __restrict__ resw, float* __restrict__ out)
{
    int tid = blockIdx.x * blockDim.x + threadIdx.x;
    if (tid >= NA * KD) return;
    float g = 1.f / (1.f + __expf(-resw[0]));
    out[tid] = g * rf_wb[tid] + (1.f - g) * out[tid];
}

// ---------------- final paper ----------------
__global__ void final_paper(const float* __restrict__ rfw, const float* __restrict__ rfc,
                            const float* __restrict__ nodep, const float* __restrict__ attnM,
                            const float* __restrict__ resw, float* __restrict__ out)
{
    int n = blockIdx.x;
    int k = threadIdx.x >> 5;
    int lane = threadIdx.x & 31;
    size_t idx = (size_t)n * KD + k * DH + lane;
    float np = nodep[idx], rw = rfw[idx], rc = rfc[idx];
    float a1 = attnM[k * 64 + lane];
    float a2 = attnM[k * 64 + 32 + lane];
    float sw = a1 * np + a2 * rw;
    float sc = a1 * np + a2 * rc;
#pragma unroll
    for (int s = 16; s > 0; s >>= 1) {
        sw += __shfl_xor_sync(0xffffffffu, sw, s);
        sc += __shfl_xor_sync(0xffffffffu, sc, s);
    }
    sw = leaky(sw);
    sc = leaky(sc);
    float mx = fmaxf(sw, sc);
    float ew = __expf(sw - mx), ec = __expf(sc - mx);
    float aw = ew / (ew + ec);
    float val = aw * rw + (1.f - aw) * rc;
    float g = 1.f / (1.f + __expf(-resw[0]));
    size_t o = (size_t)NA * KD + idx;
    out[o] = g * val + (1.f - g) * out[o];
}

// ---------------- launch ----------------
extern "C" void kernel_launch(void* const* d_in, const int* in_sizes, int n_in,
                              void* d_out, int out_size)
{
    const float* feats_author    = (const float*)d_in[0];
    const float* feats_paper     = (const float*)d_in[1];
    const float* W_micro_author  = (const float*)d_in[2];
    const float* W_micro_paper   = (const float*)d_in[3];
    const float* attn_micro_a    = (const float*)d_in[4];
    const float* attn_micro_p    = (const float*)d_in[5];
    const float* W_macro_node_p  = (const float*)d_in[7];
    const float* W_rel_writes    = (const float*)d_in[8];
    const float* W_rel_wb        = (const float*)d_in[9];
    const float* W_rel_cites     = (const float*)d_in[10];
    const float* attn_macro      = (const float*)d_in[11];
    const float* W_res_author    = (const float*)d_in[12];
    const float* b_res_author    = (const float*)d_in[13];
    const float* W_res_paper     = (const float*)d_in[14];
    const float* b_res_paper     = (const float*)d_in[15];
    const float* res_w_author    = (const float*)d_in[16];
    const float* res_w_paper     = (const float*)d_in[17];
    const int*   writes_src      = (const int*)d_in[18];
    const int*   writes_dst      = (const int*)d_in[19];
    const int*   wb_src          = (const int*)d_in[20];
    const int*   wb_dst          = (const int*)d_in[21];
    const int*   cites_src       = (const int*)d_in[22];
    const int*   cites_dst       = (const int*)d_in[23];
    float* out = (float*)d_out;

    float *PA, *PP, *elA_aA, *erP_aA, *elP_aP, *erA_aP, *erP_aP;
    float *ft_w, *ft_wb, *ft_c, *rf_w, *rf_wb, *rf_c, *nodeP;
    int *counts, *cursor, *offsets, *ssort;
    cudaGetSymbolAddress((void**)&PA, g_PA);
    cudaGetSymbolAddress((void**)&PP, g_PP);
    cudaGetSymbolAddress((void**)&elA_aA, g_elA_aA);
    cudaGetSymbolAddress((void**)&erP_aA, g_erP_aA);
    cudaGetSymbolAddress((void**)&elP_aP, g_elP_aP);
    cudaGetSymbolAddress((void**)&erA_aP, g_erA_aP);
    cudaGetSymbolAddress((void**)&erP_aP, g_erP_aP);
    cudaGetSymbolAddress((void**)&ft_w, g_ft_w);
    cudaGetSymbolAddress((void**)&ft_wb, g_ft_wb);
    cudaGetSymbolAddress((void**)&ft_c, g_ft_c);
    cudaGetSymbolAddress((void**)&rf_w, g_rf_w);
    cudaGetSymbolAddress((void**)&rf_wb, g_rf_wb);
    cudaGetSymbolAddress((void**)&rf_c, g_rf_c);
    cudaGetSymbolAddress((void**)&nodeP, g_nodeP);
    cudaGetSymbolAddress((void**)&counts, g_counts);
    cudaGetSymbolAddress((void**)&cursor, g_cursor);
    cudaGetSymbolAddress((void**)&offsets, g_offsets);
    cudaGetSymbolAddress((void**)&ssort, g_ssort);

    dim3 ggrid((NA + BM - 1) / BM, KD / BN);   // (391, 2)
    const int ZB = (50001 + 255) / 256;
    const int EB = (EDG + 255) / 256;
    const int GB = (NA * 32 + 255) / 256;

    // micro projections (tf32 mma)
    gemm_mma<<<ggrid, 256>>>(feats_author, W_micro_author, nullptr, PA, NA);
    gemm_mma<<<ggrid, 256>>>(feats_paper,  W_micro_paper,  nullptr, PP, NP);

    // fused attention dots
    attn_dots_author<<<NA, 256>>>(PA, attn_micro_a, attn_micro_p, elA_aA, erA_aP);
    attn_dots_paper <<<NP, 256>>>(PP, attn_micro_a, attn_micro_p, erP_aA, elP_aP, erP_aP);

    // --- relation: writes (author -> paper) ---
    csr_zero<<<ZB, 256>>>(counts, cursor, NP);
    csr_hist<<<EB, 256>>>(writes_dst, counts);
    csr_scan<<<1, 1024>>>(counts, offsets, NP);
    csr_scatter<<<EB, 256>>>(writes_src, writes_dst, offsets, cursor, ssort);
    micro_gather<<<GB, 256>>>(ssort, offsets, elA_aA, erP_aA, PA, ft_w, NP);

    // --- relation: written_by (paper -> author) ---
    csr_zero<<<ZB, 256>>>(counts, cursor, NA);
    csr_hist<<<EB, 256>>>(wb_dst, counts);
    csr_scan<<<1, 1024>>>(counts, offsets, NA);
    csr_scatter<<<EB, 256>>>(wb_src, wb_dst, offsets, cursor, ssort);
    micro_gather<<<GB, 256>>>(ssort, offsets, elP_aP, erA_aP, PP, ft_wb, NA);

    // --- relation: cites (paper -> paper) ---
    csr_zero<<<ZB, 256>>>(counts, cursor, NP);
    csr_hist<<<EB, 256>>>(cites_dst, counts);
    csr_scan<<<1, 1024>>>(counts, offsets, NP);
    csr_scatter<<<EB, 256>>>(cites_src, cites_dst, offsets, cursor, ssort);
    micro_gather<<<GB, 256>>>(ssort, offsets, elP_aP, erP_aP, PP, ft_c, NP);

    // macro projections (tf32 mma)
    gemm_mma<<<ggrid, 256>>>(ft_w,  W_rel_writes,  nullptr, rf_w,  NP);
    gemm_mma<<<ggrid, 256>>>(ft_wb, W_rel_wb,      nullptr, rf_wb, NA);
    gemm_mma<<<ggrid, 256>>>(ft_c,  W_rel_cites,   nullptr, rf_c,  NP);
    gemm_mma<<<ggrid, 256>>>(feats_paper, W_macro_node_p, nullptr, nodeP, NP);

    // residual projections into output halves
    gemm_mma<<<ggrid, 256>>>(feats_author, W_res_author, b_res_author, out, NA);
    gemm_mma<<<ggrid, 256>>>(feats_paper,  W_res_paper,  b_res_paper,
                             out + (size_t)NA * KD, NP);

    // final fusion
    final_author<<<(NA * KD + 255) / 256, 256>>>(rf_wb, res_w_author, out);
    final_paper<<<NP, 256>>>(rf_w, rf_c, nodeP, attn_macro, res_w_paper, out);
}

// round 5
// speedup vs baseline: 2.1482x; 1.2504x over previous
#include <cuda_runtime.h>
#include <cstdint>
#include <math.h>

// ---------------- problem constants ----------------
#define NA 50000
#define NP 50000
#define EDG 400000
#define KH 8
#define DH 32
#define KD 256
#define SLOPE 0.2f

// GEMM tiling
#define BM 128
#define BN 128
#define BK 16
#define NKT (KD / BK)      // 16
#define LDA 132
#define LDB 132

#define NBLK 196           // ceil(50000/256)

// ---------------- device scratch ----------------
__device__ float g_PA[NA * KD];
__device__ float g_PP[NP * KD];

__device__ float g_elA_aA[NA * KH];
__device__ float g_erP_aA[NP * KH];
__device__ float g_elP_aP[NP * KH];
__device__ float g_erA_aP[NA * KH];
__device__ float g_erP_aP[NP * KH];

__device__ float g_ft_w[NP * KD];
__device__ float g_ft_wb[NA * KD];
__device__ float g_ft_c[NP * KD];

__device__ float g_rf_w[NP * KD];
__device__ float g_rf_c[NP * KD];
__device__ float g_nodeP[NP * KD];

// CSR scratch
__device__ int g_counts[50000];
__device__ int g_cursor[50000];
__device__ int g_offsets[50001];
__device__ int g_partials[NBLK + 1];
__device__ int g_ssort[EDG];

// ---------------- helpers ----------------
__device__ __forceinline__ float leaky(float v) {
    return v > 0.f ? v : SLOPE * v;
}
__device__ __forceinline__ uint32_t f2tf32(float f) {
    uint32_t r;
    asm("cvt.rna.tf32.f32 %0, %1;" : "=r"(r) : "f"(f));
    return r;
}
__device__ __forceinline__ void mma_tf32(float c[4], uint32_t a0, uint32_t a1,
                                         uint32_t a2, uint32_t a3,
                                         uint32_t b0, uint32_t b1) {
    asm volatile(
        "mma.sync.aligned.m16n8k8.row.col.f32.tf32.tf32.f32 "
        "{%0,%1,%2,%3}, {%4,%5,%6,%7}, {%8,%9}, {%0,%1,%2,%3};"
        : "+f"(c[0]), "+f"(c[1]), "+f"(c[2]), "+f"(c[3])
        : "r"(a0), "r"(a1), "r"(a2), "r"(a3), "r"(b0), "r"(b1));
}

struct GemmJob {
    const float* B;
    float*       C;
    const float* bias;   // optional (+bias)
    const float* gate;   // optional: C = sig(gate)*acc + (1-sig)*C_prev
};

// ---------------- multi-output tf32 GEMM ----------------
// For each job: C[M,256 slice] = A[M,256] @ B[256,256] (+bias | gated blend)
__global__ void __launch_bounds__(256) gemm_multi(
    const float* __restrict__ A, GemmJob j0, GemmJob j1, GemmJob j2,
    int nb, int M)
{
    __shared__ uint32_t As[2][BK][LDA];
    __shared__ uint32_t Bs[2][BK][LDB];

    const int tid = threadIdx.x;
    const int lane = tid & 31;
    const int wid = tid >> 5;
    const int wm = (wid & 3) * 32;
    const int wn = (wid >> 2) * 64;
    const int n0 = blockIdx.x * BN;     // x = n-block (2) -> A L2 reuse
    const int m0 = blockIdx.y * BM;

    const int qr = lane >> 2;
    const int qc = lane & 3;

    const int am = tid >> 1;
    const int aq = (tid & 1) * 8;
    const int bk = tid >> 4;
    const int bn = (tid & 15) * 8;

    float4 rA[2], rB[2];

    auto g_load = [&](int kt, const float* __restrict__ B) {
        const int k0 = kt * BK;
        int row = m0 + am;
        if (row < M) {
            rA[0] = *(const float4*)&A[(size_t)row * KD + k0 + aq];
            rA[1] = *(const float4*)&A[(size_t)row * KD + k0 + aq + 4];
        } else {
            rA[0] = make_float4(0.f, 0.f, 0.f, 0.f);
            rA[1] = rA[0];
        }
        rB[0] = *(const float4*)&B[(size_t)(k0 + bk) * KD + n0 + bn];
        rB[1] = *(const float4*)&B[(size_t)(k0 + bk) * KD + n0 + bn + 4];
    };
    auto s_store = [&](int buf) {
        As[buf][aq + 0][am] = f2tf32(rA[0].x);
        As[buf][aq + 1][am] = f2tf32(rA[0].y);
        As[buf][aq + 2][am] = f2tf32(rA[0].z);
        As[buf][aq + 3][am] = f2tf32(rA[0].w);
        As[buf][aq + 4][am] = f2tf32(rA[1].x);
        As[buf][aq + 5][am] = f2tf32(rA[1].y);
        As[buf][aq + 6][am] = f2tf32(rA[1].z);
        As[buf][aq + 7][am] = f2tf32(rA[1].w);
        Bs[buf][bk][bn + 0] = f2tf32(rB[0].x);
        Bs[buf][bk][bn + 1] = f2tf32(rB[0].y);
        Bs[buf][bk][bn + 2] = f2tf32(rB[0].z);
        Bs[buf][bk][bn + 3] = f2tf32(rB[0].w);
        Bs[buf][bk][bn + 4] = f2tf32(rB[1].x);
        Bs[buf][bk][bn + 5] = f2tf32(rB[1].y);
        Bs[buf][bk][bn + 6] = f2tf32(rB[1].z);
        Bs[buf][bk][bn + 7] = f2tf32(rB[1].w);
    };

#pragma unroll
    for (int o = 0; o < 3; o++) {
        if (o >= nb) break;
        const GemmJob J = (o == 0) ? j0 : (o == 1) ? j1 : j2;

        float acc[2][8][4];
#pragma unroll
        for (int mi = 0; mi < 2; mi++)
#pragma unroll
            for (int ni = 0; ni < 8; ni++)
#pragma unroll
                for (int r = 0; r < 4; r++) acc[mi][ni][r] = 0.f;

        g_load(0, J.B);
        s_store(0);
        __syncthreads();

        for (int kt = 0; kt < NKT; kt++) {
            const int cur = kt & 1;
            if (kt + 1 < NKT) g_load(kt + 1, J.B);

#pragma unroll
            for (int ks = 0; ks < BK; ks += 8) {
                uint32_t a[2][4], b[8][2];
#pragma unroll
                for (int mi = 0; mi < 2; mi++) {
                    int mb = wm + mi * 16;
                    a[mi][0] = As[cur][ks + qc][mb + qr];
                    a[mi][1] = As[cur][ks + qc][mb + qr + 8];
                    a[mi][2] = As[cur][ks + qc + 4][mb + qr];
                    a[mi][3] = As[cur][ks + qc + 4][mb + qr + 8];
                }
#pragma unroll
                for (int ni = 0; ni < 8; ni++) {
                    int nb2 = wn + ni * 8;
                    b[ni][0] = Bs[cur][ks + qc][nb2 + qr];
                    b[ni][1] = Bs[cur][ks + qc + 4][nb2 + qr];
                }
#pragma unroll
                for (int mi = 0; mi < 2; mi++)
#pragma unroll
                    for (int ni = 0; ni < 8; ni++)
                        mma_tf32(acc[mi][ni], a[mi][0], a[mi][1], a[mi][2], a[mi][3],
                                 b[ni][0], b[ni][1]);
            }

            if (kt + 1 < NKT) {
                s_store(1 - cur);
                __syncthreads();
            }
        }

        float g = 0.f;
        if (J.gate) g = 1.f / (1.f + __expf(-J.gate[0]));

        // epilogue
#pragma unroll
        for (int mi = 0; mi < 2; mi++) {
#pragma unroll
            for (int half = 0; half < 2; half++) {
                int row = m0 + wm + mi * 16 + qr + half * 8;
                if (row >= M) continue;
                float* dst = &J.C[(size_t)row * KD + n0 + wn];
#pragma unroll
                for (int ni = 0; ni < 8; ni++) {
                    int col = ni * 8 + qc * 2;
                    float2 v;
                    v.x = acc[mi][ni][half * 2 + 0];
                    v.y = acc[mi][ni][half * 2 + 1];
                    if (J.bias) {
                        v.x += J.bias[n0 + wn + col + 0];
                        v.y += J.bias[n0 + wn + col + 1];
                    }
                    if (J.gate) {
                        float2 prev = *(const float2*)&dst[col];
                        v.x = g * v.x + (1.f - g) * prev.x;
                        v.y = g * v.y + (1.f - g) * prev.y;
                    }
                    *(float2*)&dst[col] = v;
                }
            }
        }
        __syncthreads();   // protect smem before next job overwrites
    }
}

// ---------------- warp-per-node attention dots ----------------
// lane L owns cols [8L, 8L+8); head = L>>2; reduce over groups of 4 lanes.
__global__ void attn_author_w(const float* __restrict__ P,
                              const float* __restrict__ attn_a,
                              const float* __restrict__ attn_p,
                              float* __restrict__ o1, float* __restrict__ o2, int N)
{
    int warp = (blockIdx.x * blockDim.x + threadIdx.x) >> 5;
    int lane = threadIdx.x & 31;
    if (warp >= N) return;
    int head = lane >> 2, sub = lane & 3;
    const float4* A1 = (const float4*)&attn_a[head * 64 + 0 + sub * 8];
    const float4* A2 = (const float4*)&attn_p[head * 64 + 32 + sub * 8];
    float4 a10 = A1[0], a11 = A1[1], a20 = A2[0], a21 = A2[1];
    const float4* p = (const float4*)&P[(size_t)warp * KD + lane * 8];
    float4 p0 = p[0], p1 = p[1];
    float v1 = p0.x * a10.x + p0.y * a10.y + p0.z * a10.z + p0.w * a10.w
             + p1.x * a11.x + p1.y * a11.y + p1.z * a11.z + p1.w * a11.w;
    float v2 = p0.x * a20.x + p0.y * a20.y + p0.z * a20.z + p0.w * a20.w
             + p1.x * a21.x + p1.y * a21.y + p1.z * a21.z + p1.w * a21.w;
    v1 += __shfl_xor_sync(0xffffffffu, v1, 1);
    v1 += __shfl_xor_sync(0xffffffffu, v1, 2);
    v2 += __shfl_xor_sync(0xffffffffu, v2, 1);
    v2 += __shfl_xor_sync(0xffffffffu, v2, 2);
    if (sub == 0) {
        o1[warp * KH + head] = v1;
        o2[warp * KH + head] = v2;
    }
}

__global__ void attn_paper_w(const float* __restrict__ P,
                             const float* __restrict__ attn_a,
                             const float* __restrict__ attn_p,
                             float* __restrict__ o1, float* __restrict__ o2,
                             float* __restrict__ o3, int N)
{
    int warp = (blockIdx.x * blockDim.x + threadIdx.x) >> 5;
    int lane = threadIdx.x & 31;
    if (warp >= N) return;
    int head = lane >> 2, sub = lane & 3;
    const float4* A1 = (const float4*)&attn_a[head * 64 + 32 + sub * 8];
    const float4* A2 = (const float4*)&attn_p[head * 64 + 0 + sub * 8];
    const float4* A3 = (const float4*)&attn_p[head * 64 + 32 + sub * 8];
    float4 a10 = A1[0], a11 = A1[1];
    float4 a20 = A2[0], a21 = A2[1];
    float4 a30 = A3[0], a31 = A3[1];
    const float4* p = (const float4*)&P[(size_t)warp * KD + lane * 8];
    float4 p0 = p[0], p1 = p[1];
    float v1 = p0.x * a10.x + p0.y * a10.y + p0.z * a10.z + p0.w * a10.w
             + p1.x * a11.x + p1.y * a11.y + p1.z * a11.z + p1.w * a11.w;
    float v2 = p0.x * a20.x + p0.y * a20.y + p0.z * a20.z + p0.w * a20.w
             + p1.x * a21.x + p1.y * a21.y + p1.z * a21.z + p1.w * a21.w;
    float v3 = p0.x * a30.x + p0.y * a30.y + p0.z * a30.z + p0.w * a30.w
             + p1.x * a31.x + p1.y * a31.y + p1.z * a31.z + p1.w * a31.w;
    v1 += __shfl_xor_sync(0xffffffffu, v1, 1);
    v1 += __shfl_xor_sync(0xffffffffu, v1, 2);
    v2 += __shfl_xor_sync(0xffffffffu, v2, 1);
    v2 += __shfl_xor_sync(0xffffffffu, v2, 2);
    v3 += __shfl_xor_sync(0xffffffffu, v3, 1);
    v3 += __shfl_xor_sync(0xffffffffu, v3, 2);
    if (sub == 0) {
        o1[warp * KH + head] = v1;
        o2[warp * KH + head] = v2;
        o3[warp * KH + head] = v3;
    }
}

// ---------------- CSR build ----------------
__global__ void csr_hist(const int* __restrict__ dst, int* __restrict__ counts)
{
    int e = blockIdx.x * blockDim.x + threadIdx.x;
    if (e < EDG) atomicAdd(&counts[dst[e]], 1);
}

// two-level exclusive scan
__global__ void scan_block(const int* __restrict__ in, int* __restrict__ out,
                           int* __restrict__ partials, int n)
{
    __shared__ int wsum[8];
    int i = blockIdx.x * 256 + threadIdx.x;
    int lane = threadIdx.x & 31, wid = threadIdx.x >> 5;
    int v = (i < n) ? in[i] : 0;
    int x = v;
#pragma unroll
    for (int o = 1; o < 32; o <<= 1) {
        int t = __shfl_up_sync(0xffffffffu, x, o);
        if (lane >= o) x += t;
    }
    if (lane == 31) wsum[wid] = x;
    __syncthreads();
    if (wid == 0) {
        int w = (lane < 8) ? wsum[lane] : 0;
#pragma unroll
        for (int o = 1; o < 8; o <<= 1) {
            int t = __shfl_up_sync(0xffffffffu, w, o);
            if (lane >= o) w += t;
        }
        if (lane < 8) wsum[lane] = w;
    }
    __syncthreads();
    int wpre = (wid > 0) ? wsum[wid - 1] : 0;
    if (i < n) out[i] = wpre + x - v;
    if (threadIdx.x == 0) partials[blockIdx.x] = wsum[7];
}

__global__ void scan_top(int* __restrict__ partials, int nb)
{
    __shared__ int wsum[8];
    int i = threadIdx.x;
    int lane = i & 31, wid = i >> 5;
    int v = (i < nb) ? partials[i] : 0;
    int x = v;
#pragma unroll
    for (int o = 1; o < 32; o <<= 1) {
        int t = __shfl_up_sync(0xffffffffu, x, o);
        if (lane >= o) x += t;
    }
    if (lane == 31) wsum[wid] = x;
    __syncthreads();
    if (wid == 0) {
        int w = (lane < 8) ? wsum[lane] : 0;
#pragma unroll
        for (int o = 1; o < 8; o <<= 1) {
            int t = __shfl_up_sync(0xffffffffu, w, o);
            if (lane >= o) w += t;
        }
        if (lane < 8) wsum[lane] = w;
    }
    __syncthreads();
    int wpre = (wid > 0) ? wsum[wid - 1] : 0;
    if (i < nb) partials[i] = wpre + x - v;
    if (i == 0) partials[nb] = wsum[7];
}

__global__ void scan_add(int* __restrict__ offsets, const int* __restrict__ partials, int n)
{
    int i = blockIdx.x * 256 + threadIdx.x;
    if (i < n) offsets[i] += partials[blockIdx.x];
    if (i == 0) offsets[n] = partials[gridDim.x];
}

__global__ void csr_scatter(const int* __restrict__ src, const int* __restrict__ dst,
                            const int* __restrict__ offsets, int* __restrict__ cursor,
                            int* __restrict__ ssort)
{
    int e = blockIdx.x * blockDim.x + threadIdx.x;
    if (e >= EDG) return;
    int d = dst[e];
    int pos = offsets[d] + atomicAdd(&cursor[d], 1);
    ssort[pos] = src[e];
}

// ---------------- fused micro gather: softmax + weighted sum + relu ----------------
__global__ void micro_gather(const int* __restrict__ ssort, const int* __restrict__ offsets,
                             const float* __restrict__ el, const float* __restrict__ er,
                             const float* __restrict__ Psrc, float* __restrict__ ft, int n_dst)
{
    int d = (blockIdx.x * blockDim.x + threadIdx.x) >> 5;
    int lane = threadIdx.x & 31;
    if (d >= n_dst) return;
    int beg = offsets[d], end = offsets[d + 1];
    float* dstp = &ft[(size_t)d * KD + lane * 8];
    if (beg == end) {
        float4 z = make_float4(0.f, 0.f, 0.f, 0.f);
        *(float4*)dstp = z;
        *(float4*)(dstp + 4) = z;
        return;
    }
    float erv = (lane < KH) ? er[d * KH + lane] : 0.f;

    float mx = -1e30f;
    for (int i = beg; i < end; i++) {
        int s = ssort[i];
        if (lane < KH) mx = fmaxf(mx, leaky(el[s * KH + lane] + erv));
    }

    const int hk = lane >> 2;
    float acc[8] = {0.f, 0.f, 0.f, 0.f, 0.f, 0.f, 0.f, 0.f};
    float se = 0.f;
    for (int i = beg; i < end; i++) {
        int s = ssort[i];
        float w = 0.f;
        if (lane < KH) {
            w = __expf(leaky(el[s * KH + lane] + erv) - mx);
            se += w;
        }
        float wk = __shfl_sync(0xffffffffu, w, hk);
        const float4* p = (const float4*)&Psrc[(size_t)s * KD + lane * 8];
        float4 p0 = p[0], p1 = p[1];
        acc[0] = fmaf(wk, p0.x, acc[0]);
        acc[1] = fmaf(wk, p0.y, acc[1]);
        acc[2] = fmaf(wk, p0.z, acc[2]);
        acc[3] = fmaf(wk, p0.w, acc[3]);
        acc[4] = fmaf(wk, p1.x, acc[4]);
        acc[5] = fmaf(wk, p1.y, acc[5]);
        acc[6] = fmaf(wk, p1.z, acc[6]);
        acc[7] = fmaf(wk, p1.w, acc[7]);
    }
    float inv = 1.f / __shfl_sync(0xffffffffu, se, hk);
    float4 o0, o1;
    o0.x = fmaxf(acc[0] * inv, 0.f);
    o0.y = fmaxf(acc[1] * inv, 0.f);
    o0.z = fmaxf(acc[2] * inv, 0.f);
    o0.w = fmaxf(acc[3] * inv, 0.f);
    o1.x = fmaxf(acc[4] * inv, 0.f);
    o1.y = fmaxf(acc[5] * inv, 0.f);
    o1.z = fmaxf(acc[6] * inv, 0.f);
    o1.w = fmaxf(acc[7] * inv, 0.f);
    *(float4*)dstp = o0;
    *(float4*)(dstp + 4) = o1;
}

// ---------------- final paper: semantic attention + gated residual ----------------
__global__ void final_paper(const float* __restrict__ rfw, const float* __restrict__ rfc,
                            const float* __restrict__ nodep, const float* __restrict__ attnM,
                            const float* __restrict__ resw, float* __restrict__ out)
{
    int n = blockIdx.x;
    int k = threadIdx.x >> 5;
    int lane = threadIdx.x & 31;
    size_t idx = (size_t)n * KD + k * DH + lane;
    float np = nodep[idx], rw = rfw[idx], rc = rfc[idx];
    float a1 = attnM[k * 64 + lane];
    float a2 = attnM[k * 64 + 32 + lane];
    float sw = a1 * np + a2 * rw;
    float sc = a1 * np + a2 * rc;
#pragma unroll
    for (int s = 16; s > 0; s >>= 1) {
        sw += __shfl_xor_sync(0xffffffffu, sw, s);
        sc += __shfl_xor_sync(0xffffffffu, sc, s);
    }
    sw = leaky(sw);
    sc = leaky(sc);
    float mx = fmaxf(sw, sc);
    float ew = __expf(sw - mx), ec = __expf(sc - mx);
    float aw = ew / (ew + ec);
    float val = aw * rw + (1.f - aw) * rc;
    float g = 1.f / (1.f + __expf(-resw[0]));
    size_t o = (size_t)NA * KD + idx;
    out[o] = g * val + (1.f - g) * out[o];
}

// ---------------- launch ----------------
extern "C" void kernel_launch(void* const* d_in, const int* in_sizes, int n_in,
                              void* d_out, int out_size)
{
    const float* feats_author    = (const float*)d_in[0];
    const float* feats_paper     = (const float*)d_in[1];
    const float* W_micro_author  = (const float*)d_in[2];
    const float* W_micro_paper   = (const float*)d_in[3];
    const float* attn_micro_a    = (const float*)d_in[4];
    const float* attn_micro_p    = (const float*)d_in[5];
    const float* W_macro_node_p  = (const float*)d_in[7];
    const float* W_rel_writes    = (const float*)d_in[8];
    const float* W_rel_wb        = (const float*)d_in[9];
    const float* W_rel_cites     = (const float*)d_in[10];
    const float* attn_macro      = (const float*)d_in[11];
    const float* W_res_author    = (const float*)d_in[12];
    const float* b_res_author    = (const float*)d_in[13];
    const float* W_res_paper     = (const float*)d_in[14];
    const float* b_res_paper     = (const float*)d_in[15];
    const float* res_w_author    = (const float*)d_in[16];
    const float* res_w_paper     = (const float*)d_in[17];
    const int*   writes_src      = (const int*)d_in[18];
    const int*   writes_dst      = (const int*)d_in[19];
    const int*   wb_src          = (const int*)d_in[20];
    const int*   wb_dst          = (const int*)d_in[21];
    const int*   cites_src       = (const int*)d_in[22];
    const int*   cites_dst       = (const int*)d_in[23];
    float* out = (float*)d_out;

    float *PA, *PP, *elA_aA, *erP_aA, *elP_aP, *erA_aP, *erP_aP;
    float *ft_w, *ft_wb, *ft_c, *rf_w, *rf_c, *nodeP;
    int *counts, *cursor, *offsets, *partials, *ssort;
    cudaGetSymbolAddress((void**)&PA, g_PA);
    cudaGetSymbolAddress((void**)&PP, g_PP);
    cudaGetSymbolAddress((void**)&elA_aA, g_elA_aA);
    cudaGetSymbolAddress((void**)&erP_aA, g_erP_aA);
    cudaGetSymbolAddress((void**)&elP_aP, g_elP_aP);
    cudaGetSymbolAddress((void**)&erA_aP, g_erA_aP);
    cudaGetSymbolAddress((void**)&erP_aP, g_erP_aP);
    cudaGetSymbolAddress((void**)&ft_w, g_ft_w);
    cudaGetSymbolAddress((void**)&ft_wb, g_ft_wb);
    cudaGetSymbolAddress((void**)&ft_c, g_ft_c);
    cudaGetSymbolAddress((void**)&rf_w, g_rf_w);
    cudaGetSymbolAddress((void**)&rf_c, g_rf_c);
    cudaGetSymbolAddress((void**)&nodeP, g_nodeP);
    cudaGetSymbolAddress((void**)&counts, g_counts);
    cudaGetSymbolAddress((void**)&cursor, g_cursor);
    cudaGetSymbolAddress((void**)&offsets, g_offsets);
    cudaGetSymbolAddress((void**)&partials, g_partials);
    cudaGetSymbolAddress((void**)&ssort, g_ssort);

    dim3 ggrid(KD / BN, (NA + BM - 1) / BM);   // (2, 391): n fastest -> A L2 reuse
    const int EB = (EDG + 255) / 256;
    const int GB = (NA * 32 + 255) / 256;
    const int WB = (NA * 32 + 255) / 256;

    GemmJob jz = { nullptr, nullptr, nullptr, nullptr };

    // author group: micro projection + residual (with bias) -> out[:NA]
    {
        GemmJob ja = { W_micro_author, PA, nullptr, nullptr };
        GemmJob jb = { W_res_author, out, b_res_author, nullptr };
        gemm_multi<<<ggrid, 256>>>(feats_author, ja, jb, jz, 2, NA);
    }
    // paper group: micro + macro-node + residual (with bias) -> out[NA:]
    {
        GemmJob ja = { W_micro_paper, PP, nullptr, nullptr };
        GemmJob jb = { W_macro_node_p, nodeP, nullptr, nullptr };
        GemmJob jc = { W_res_paper, out + (size_t)NA * KD, b_res_paper, nullptr };
        gemm_multi<<<ggrid, 256>>>(feats_paper, ja, jb, jc, 3, NP);
    }

    // attention dots (warp per node)
    attn_author_w<<<WB, 256>>>(PA, attn_micro_a, attn_micro_p, elA_aA, erA_aP, NA);
    attn_paper_w <<<WB, 256>>>(PP, attn_micro_a, attn_micro_p, erP_aA, elP_aP, erP_aP, NP);

    // --- per-relation CSR + gather ---
    struct Rel { const int* src; const int* dst; const float* el; const float* er;
                 const float* P; float* ft; int n; };
    Rel rels[3] = {
        { writes_src, writes_dst, elA_aA, erP_aA, PA, ft_w,  NP },
        { wb_src,     wb_dst,     elP_aP, erA_aP, PP, ft_wb, NA },
        { cites_src,  cites_dst,  elP_aP, erP_aP, PP, ft_c,  NP },
    };
    for (int r = 0; r < 3; r++) {
        Rel& R = rels[r];
        cudaMemsetAsync(counts, 0, R.n * sizeof(int));
        cudaMemsetAsync(cursor, 0, R.n * sizeof(int));
        csr_hist<<<EB, 256>>>(R.dst, counts);
        scan_block<<<NBLK, 256>>>(counts, offsets, partials, R.n);
        scan_top<<<1, 256>>>(partials, NBLK);
        scan_add<<<NBLK, 256>>>(offsets, partials, R.n);
        csr_scatter<<<EB, 256>>>(R.src, R.dst, offsets, cursor, ssort);
        micro_gather<<<GB, 256>>>(ssort, offsets, R.el, R.er, R.P, R.ft, R.n);
    }

    // macro projections
    {
        GemmJob ja = { W_rel_writes, rf_w, nullptr, nullptr };
        gemm_multi<<<ggrid, 256>>>(ft_w, ja, jz, jz, 1, NP);
    }
    {
        GemmJob ja = { W_rel_cites, rf_c, nullptr, nullptr };
        gemm_multi<<<ggrid, 256>>>(ft_c, ja, jz, jz, 1, NP);
    }
    {
        // written_by macro projection with fused gated residual into out[:NA]
        GemmJob ja = { W_rel_wb, out, nullptr, res_w_author };
        gemm_multi<<<ggrid, 256>>>(ft_wb, ja, jz, jz, 1, NA);
    }

    // final paper fusion (semantic attention + gated residual)
    final_paper<<<NP, 256>>>(rf_w, rf_c, nodeP, attn_macro, res_w_paper, out);
}

// round 6
// speedup vs baseline: 2.3714x; 1.1039x over previous
#include <cuda_runtime.h>
#include <cstdint>
#include <math.h>

// ---------------- problem constants ----------------
#define NA 50000
#define NP 50000
#define EDG 400000
#define KH 8
#define DH 32
#define KD 256
#define SLOPE 0.2f

// GEMM tiling: block 128(M) x 256(N), 8 warps (2m x 4n), warp 64x64, BK=16
#define BM 128
#define BK 16
#define NKT (KD / BK)      // 16
#define LDK 20             // A smem row stride ([m][k] layout)
#define LDBN 264           // B smem row stride ([k][n] layout)
#define ASZ (128 * LDK)    // 2560 u32 per A buffer
#define BSZ (BK * LDBN)    // 4224 u32 per B buffer
#define SMEM_BYTES ((2 * ASZ + 2 * BSZ) * 4)   // 54272

#define NBLK 196           // ceil(50000/256)

// ---------------- device scratch ----------------
__device__ float g_PA[NA * KD];
__device__ float g_PP[NP * KD];

__device__ float g_elA_aA[NA * KH];
__device__ float g_erP_aA[NP * KH];
__device__ float g_elP_aP[NP * KH];
__device__ float g_erA_aP[NA * KH];
__device__ float g_erP_aP[NP * KH];

__device__ float g_ft_w[NP * KD];
__device__ float g_ft_wb[NA * KD];
__device__ float g_ft_c[NP * KD];

__device__ float g_rf_w[NP * KD];
__device__ float g_rf_c[NP * KD];
__device__ float g_nodeP[NP * KD];

// CSR scratch
__device__ int g_counts[50000];
__device__ int g_cursor[50000];
__device__ int g_offsets[50001];
__device__ int g_partials[NBLK + 1];
__device__ int g_ssort[EDG];

// ---------------- helpers ----------------
__device__ __forceinline__ float leaky(float v) {
    return v > 0.f ? v : SLOPE * v;
}
__device__ __forceinline__ uint32_t f2tf32(float f) {
    uint32_t r;
    asm("cvt.rna.tf32.f32 %0, %1;" : "=r"(r) : "f"(f));
    return r;
}
__device__ __forceinline__ void mma_tf32(float c[4], uint32_t a0, uint32_t a1,
                                         uint32_t a2, uint32_t a3,
                                         uint32_t b0, uint32_t b1) {
    asm volatile(
        "mma.sync.aligned.m16n8k8.row.col.f32.tf32.tf32.f32 "
        "{%0,%1,%2,%3}, {%4,%5,%6,%7}, {%8,%9}, {%0,%1,%2,%3};"
        : "+f"(c[0]), "+f"(c[1]), "+f"(c[2]), "+f"(c[3])
        : "r"(a0), "r"(a1), "r"(a2), "r"(a3), "r"(b0), "r"(b1));
}

struct GemmJob {
    const float* A;
    const float* B;
    float*       C;
    const float* bias;   // optional
    const float* gate;   // optional gated blend: C = sig(g)*acc + (1-sig)*C_prev
    const float* av0; float* ao0;   // optional fused attn dots (av = attn base + off)
    const float* av1; float* ao1;
    const float* av2; float* ao2;
};

// ---------------- multi-job tf32 GEMM: per job C[M,256] = A[M,256] @ B[256,256] ----------------
// block: 128 rows x full 256 cols. 8 warps, warp tile 64x64.
__global__ void __launch_bounds__(256, 1) gemm_multi(
    GemmJob j0, GemmJob j1, GemmJob j2, int nb, int M)
{
    extern __shared__ uint32_t smem[];
    // As: [buf][m:128][k:16] stride LDK ; Bs: [buf][k:16][n:256] stride LDBN
    const int tid = threadIdx.x;
    const int lane = tid & 31;
    const int wid = tid >> 5;
    const int wm = (wid & 1) * 64;
    const int wn = (wid >> 1) * 64;
    const int m0 = blockIdx.x * BM;

    const int qr = lane >> 2;   // 0..7
    const int qc = lane & 3;    // 0..3

    // global->smem load assignment
    const int am = tid >> 1;           // A row 0..127
    const int aq = (tid & 1) * 8;      // A k offset 0 or 8
    const int bkr = tid >> 4;          // B k row 0..15
    const int bnc = (tid & 15) * 16;   // B n offset 0..240

    float4 rA[2], rB[4];

    auto g_load = [&](int kt, const float* __restrict__ A, const float* __restrict__ B) {
        const int k0 = kt * BK;
        int row = m0 + am;
        if (row < M) {
            rA[0] = *(const float4*)&A[(size_t)row * KD + k0 + aq];
            rA[1] = *(const float4*)&A[(size_t)row * KD + k0 + aq + 4];
        } else {
            rA[0] = make_float4(0.f, 0.f, 0.f, 0.f);
            rA[1] = rA[0];
        }
        const float* bp = &B[(size_t)(k0 + bkr) * KD + bnc];
        rB[0] = *(const float4*)&bp[0];
        rB[1] = *(const float4*)&bp[4];
        rB[2] = *(const float4*)&bp[8];
        rB[3] = *(const float4*)&bp[12];
    };
    auto s_store = [&](int buf) {
        uint32_t* as = &smem[buf * ASZ + am * LDK + aq];
        uint4 v0, v1;
        v0.x = f2tf32(rA[0].x); v0.y = f2tf32(rA[0].y);
        v0.z = f2tf32(rA[0].z); v0.w = f2tf32(rA[0].w);
        v1.x = f2tf32(rA[1].x); v1.y = f2tf32(rA[1].y);
        v1.z = f2tf32(rA[1].z); v1.w = f2tf32(rA[1].w);
        *(uint4*)&as[0] = v0;
        *(uint4*)&as[4] = v1;
        uint32_t* bs = &smem[2 * ASZ + buf * BSZ + bkr * LDBN + bnc];
#pragma unroll
        for (int q = 0; q < 4; q++) {
            uint4 w;
            w.x = f2tf32(((const float*)&rB[q])[0]);
            w.y = f2tf32(((const float*)&rB[q])[1]);
            w.z = f2tf32(((const float*)&rB[q])[2]);
            w.w = f2tf32(((const float*)&rB[q])[3]);
            *(uint4*)&bs[q * 4] = w;
        }
    };

#pragma unroll
    for (int o = 0; o < 3; o++) {
        if (o >= nb) break;
        const GemmJob J = (o == 0) ? j0 : (o == 1) ? j1 : j2;

        float acc[4][8][4];
#pragma unroll
        for (int mi = 0; mi < 4; mi++)
#pragma unroll
            for (int ni = 0; ni < 8; ni++)
#pragma unroll
                for (int r = 0; r < 4; r++) acc[mi][ni][r] = 0.f;

        g_load(0, J.A, J.B);
        s_store(0);
        __syncthreads();

        for (int kt = 0; kt < NKT; kt++) {
            const int cur = kt & 1;
            if (kt + 1 < NKT) g_load(kt + 1, J.A, J.B);

            const uint32_t* asb = &smem[cur * ASZ];
            const uint32_t* bsb = &smem[2 * ASZ + cur * BSZ];
#pragma unroll
            for (int ks = 0; ks < BK; ks += 8) {
                uint32_t a[4][4], b[8][2];
#pragma unroll
                for (int mi = 0; mi < 4; mi++) {
                    int r0 = wm + mi * 16 + qr;
                    a[mi][0] = asb[r0 * LDK + ks + qc];
                    a[mi][1] = asb[(r0 + 8) * LDK + ks + qc];
                    a[mi][2] = asb[r0 * LDK + ks + qc + 4];
                    a[mi][3] = asb[(r0 + 8) * LDK + ks + qc + 4];
                }
#pragma unroll
                for (int ni = 0; ni < 8; ni++) {
                    int c0 = wn + ni * 8 + qr;
                    b[ni][0] = bsb[(ks + qc) * LDBN + c0];
                    b[ni][1] = bsb[(ks + qc + 4) * LDBN + c0];
                }
#pragma unroll
                for (int mi = 0; mi < 4; mi++)
#pragma unroll
                    for (int ni = 0; ni < 8; ni++)
                        mma_tf32(acc[mi][ni], a[mi][0], a[mi][1], a[mi][2], a[mi][3],
                                 b[ni][0], b[ni][1]);
            }

            if (kt + 1 < NKT) {
                s_store(1 - cur);
                __syncthreads();
            }
        }

        // ---- fused attention dots (micro jobs) ----
        if (J.av0) {
            const float* avs[3] = { J.av0, J.av1, J.av2 };
            float*       aos[3] = { J.ao0, J.ao1, J.ao2 };
            const int h0 = wn >> 5;
#pragma unroll
            for (int t = 0; t < 3; t++) {
                const float* av = avs[t];
                if (!av) break;
                float* ao = aos[t];
                float c0[8], c1[8];
#pragma unroll
                for (int ni = 0; ni < 8; ni++) {
                    int col = wn + ni * 8 + qc * 2;
                    int idx = (col >> 5) * 64 + (col & 31);
                    c0[ni] = av[idx];
                    c1[ni] = av[idx + 1];
                }
#pragma unroll
                for (int mi = 0; mi < 4; mi++) {
#pragma unroll
                    for (int half = 0; half < 2; half++) {
                        float pa = 0.f, pb = 0.f;
#pragma unroll
                        for (int ni = 0; ni < 4; ni++)
                            pa += acc[mi][ni][half * 2] * c0[ni]
                                + acc[mi][ni][half * 2 + 1] * c1[ni];
#pragma unroll
                        for (int ni = 4; ni < 8; ni++)
                            pb += acc[mi][ni][half * 2] * c0[ni]
                                + acc[mi][ni][half * 2 + 1] * c1[ni];
                        pa += __shfl_xor_sync(0xffffffffu, pa, 1);
                        pa += __shfl_xor_sync(0xffffffffu, pa, 2);
                        pb += __shfl_xor_sync(0xffffffffu, pb, 1);
                        pb += __shfl_xor_sync(0xffffffffu, pb, 2);
                        int row = m0 + wm + mi * 16 + qr + half * 8;
                        if (qc == 0 && row < M) {
                            ao[row * KH + h0]     = pa;
                            ao[row * KH + h0 + 1] = pb;
                        }
                    }
                }
            }
        }

        float g = 0.f;
        if (J.gate) g = 1.f / (1.f + __expf(-J.gate[0]));

        // ---- C epilogue ----
#pragma unroll
        for (int mi = 0; mi < 4; mi++) {
#pragma unroll
            for (int half = 0; half < 2; half++) {
                int row = m0 + wm + mi * 16 + qr + half * 8;
                if (row >= M) continue;
                float* dst = &J.C[(size_t)row * KD + wn];
#pragma unroll
                for (int ni = 0; ni < 8; ni++) {
                    int col = ni * 8 + qc * 2;
                    float2 v;
                    v.x = acc[mi][ni][half * 2 + 0];
                    v.y = acc[mi][ni][half * 2 + 1];
                    if (J.bias) {
                        v.x += J.bias[wn + col + 0];
                        v.y += J.bias[wn + col + 1];
                    }
                    if (J.gate) {
                        float2 prev = *(const float2*)&dst[col];
                        v.x = g * v.x + (1.f - g) * prev.x;
                        v.y = g * v.y + (1.f - g) * prev.y;
                    }
                    *(float2*)&dst[col] = v;
                }
            }
        }
        __syncthreads();
    }
}

// ---------------- CSR build ----------------
__global__ void csr_hist(const int* __restrict__ dst, int* __restrict__ counts)
{
    int e = blockIdx.x * blockDim.x + threadIdx.x;
    if (e < EDG) atomicAdd(&counts[dst[e]], 1);
}

__global__ void scan_block(const int* __restrict__ in, int* __restrict__ out,
                           int* __restrict__ partials, int n)
{
    __shared__ int wsum[8];
    int i = blockIdx.x * 256 + threadIdx.x;
    int lane = threadIdx.x & 31, wid = threadIdx.x >> 5;
    int v = (i < n) ? in[i] : 0;
    int x = v;
#pragma unroll
    for (int o = 1; o < 32; o <<= 1) {
        int t = __shfl_up_sync(0xffffffffu, x, o);
        if (lane >= o) x += t;
    }
    if (lane == 31) wsum[wid] = x;
    __syncthreads();
    if (wid == 0) {
        int w = (lane < 8) ? wsum[lane] : 0;
#pragma unroll
        for (int o = 1; o < 8; o <<= 1) {
            int t = __shfl_up_sync(0xffffffffu, w, o);
            if (lane >= o) w += t;
        }
        if (lane < 8) wsum[lane] = w;
    }
    __syncthreads();
    int wpre = (wid > 0) ? wsum[wid - 1] : 0;
    if (i < n) out[i] = wpre + x - v;
    if (threadIdx.x == 0) partials[blockIdx.x] = wsum[7];
}

__global__ void scan_top(int* __restrict__ partials, int nb)
{
    __shared__ int wsum[8];
    int i = threadIdx.x;
    int lane = i & 31, wid = i >> 5;
    int v = (i < nb) ? partials[i] : 0;
    int x = v;
#pragma unroll
    for (int o = 1; o < 32; o <<= 1) {
        int t = __shfl_up_sync(0xffffffffu, x, o);
        if (lane >= o) x += t;
    }
    if (lane == 31) wsum[wid] = x;
    __syncthreads();
    if (wid == 0) {
        int w = (lane < 8) ? wsum[lane] : 0;
#pragma unroll
        for (int o = 1; o < 8; o <<= 1) {
            int t = __shfl_up_sync(0xffffffffu, w, o);
            if (lane >= o) w += t;
        }
        if (lane < 8) wsum[lane] = w;
    }
    __syncthreads();
    int wpre = (wid > 0) ? wsum[wid - 1] : 0;
    if (i < nb) partials[i] = wpre + x - v;
    if (i == 0) partials[nb] = wsum[7];
}

__global__ void scan_add(int* __restrict__ offsets, const int* __restrict__ partials, int n)
{
    int i = blockIdx.x * 256 + threadIdx.x;
    if (i < n) offsets[i] += partials[blockIdx.x];
    if (i == 0) offsets[n] = partials[gridDim.x];
}

__global__ void csr_scatter(const int* __restrict__ src, const int* __restrict__ dst,
                            const int* __restrict__ offsets, int* __restrict__ cursor,
                            int* __restrict__ ssort)
{
    int e = blockIdx.x * blockDim.x + threadIdx.x;
    if (e >= EDG) return;
    int d = dst[e];
    int pos = offsets[d] + atomicAdd(&cursor[d], 1);
    ssort[pos] = src[e];
}

// ---------------- fused micro gather: softmax + weighted sum + relu ----------------
__global__ void micro_gather(const int* __restrict__ ssort, const int* __restrict__ offsets,
                             const float* __restrict__ el, const float* __restrict__ er,
                             const float* __restrict__ Psrc, float* __restrict__ ft, int n_dst)
{
    int d = (blockIdx.x * blockDim.x + threadIdx.x) >> 5;
    int lane = threadIdx.x & 31;
    if (d >= n_dst) return;
    int beg = offsets[d], end = offsets[d + 1];
    float* dstp = &ft[(size_t)d * KD + lane * 8];
    if (beg == end) {
        float4 z = make_float4(0.f, 0.f, 0.f, 0.f);
        *(float4*)dstp = z;
        *(float4*)(dstp + 4) = z;
        return;
    }
    float erv = (lane < KH) ? er[d * KH + lane] : 0.f;

    float mx = -1e30f;
    for (int i = beg; i < end; i++) {
        int s = ssort[i];
        if (lane < KH) mx = fmaxf(mx, leaky(el[s * KH + lane] + erv));
    }

    const int hk = lane >> 2;
    float acc[8] = {0.f, 0.f, 0.f, 0.f, 0.f, 0.f, 0.f, 0.f};
    float se = 0.f;
    for (int i = beg; i < end; i++) {
        int s = ssort[i];
        float w = 0.f;
        if (lane < KH) {
            w = __expf(leaky(el[s * KH + lane] + erv) - mx);
            se += w;
        }
        float wk = __shfl_sync(0xffffffffu, w, hk);
        const float4* p = (const float4*)&Psrc[(size_t)s * KD + lane * 8];
        float4 p0 = p[0], p1 = p[1];
        acc[0] = fmaf(wk, p0.x, acc[0]);
        acc[1] = fmaf(wk, p0.y, acc[1]);
        acc[2] = fmaf(wk, p0.z, acc[2]);
        acc[3] = fmaf(wk, p0.w, acc[3]);
        acc[4] = fmaf(wk, p1.x, acc[4]);
        acc[5] = fmaf(wk, p1.y, acc[5]);
        acc[6] = fmaf(wk, p1.z, acc[6]);
        acc[7] = fmaf(wk, p1.w, acc[7]);
    }
    float inv = 1.f / __shfl_sync(0xffffffffu, se, hk);
    float4 o0, o1;
    o0.x = fmaxf(acc[0] * inv, 0.f);
    o0.y = fmaxf(acc[1] * inv, 0.f);
    o0.z = fmaxf(acc[2] * inv, 0.f);
    o0.w = fmaxf(acc[3] * inv, 0.f);
    o1.x = fmaxf(acc[4] * inv, 0.f);
    o1.y = fmaxf(acc[5] * inv, 0.f);
    o1.z = fmaxf(acc[6] * inv, 0.f);
    o1.w = fmaxf(acc[7] * inv, 0.f);
    *(float4*)dstp = o0;
    *(float4*)(dstp + 4) = o1;
}

// ---------------- final paper: semantic attention + gated residual ----------------
__global__ void final_paper(const float* __restrict__ rfw, const float* __restrict__ rfc,
                            const float* __restrict__ nodep, const float* __restrict__ attnM,
                            const float* __restrict__ resw, float* __restrict__ out)
{
    int n = blockIdx.x;
    int k = threadIdx.x >> 5;
    int lane = threadIdx.x & 31;
    size_t idx = (size_t)n * KD + k * DH + lane;
    float np = nodep[idx], rw = rfw[idx], rc = rfc[idx];
    float a1 = attnM[k * 64 + lane];
    float a2 = attnM[k * 64 + 32 + lane];
    float sw = a1 * np + a2 * rw;
    float sc = a1 * np + a2 * rc;
#pragma unroll
    for (int s = 16; s > 0; s >>= 1) {
        sw += __shfl_xor_sync(0xffffffffu, sw, s);
        sc += __shfl_xor_sync(0xffffffffu, sc, s);
    }
    sw = leaky(sw);
    sc = leaky(sc);
    float mx = fmaxf(sw, sc);
    float ew = __expf(sw - mx), ec = __expf(sc - mx);
    float aw = ew / (ew + ec);
    float val = aw * rw + (1.f - aw) * rc;
    float g = 1.f / (1.f + __expf(-resw[0]));
    size_t o = (size_t)NA * KD + idx;
    out[o] = g * val + (1.f - g) * out[o];
}

// ---------------- launch ----------------
extern "C" void kernel_launch(void* const* d_in, const int* in_sizes, int n_in,
                              void* d_out, int out_size)
{
    const float* feats_author    = (const float*)d_in[0];
    const float* feats_paper     = (const float*)d_in[1];
    const float* W_micro_author  = (const float*)d_in[2];
    const float* W_micro_paper   = (const float*)d_in[3];
    const float* attn_micro_a    = (const float*)d_in[4];
    const float* attn_micro_p    = (const float*)d_in[5];
    const float* W_macro_node_p  = (const float*)d_in[7];
    const float* W_rel_writes    = (const float*)d_in[8];
    const float* W_rel_wb        = (const float*)d_in[9];
    const float* W_rel_cites     = (const float*)d_in[10];
    const float* attn_macro      = (const float*)d_in[11];
    const float* W_res_author    = (const float*)d_in[12];
    const float* b_res_author    = (const float*)d_in[13];
    const float* W_res_paper     = (const float*)d_in[14];
    const float* b_res_paper     = (const float*)d_in[15];
    const float* res_w_author    = (const float*)d_in[16];
    const float* res_w_paper     = (const float*)d_in[17];
    const int*   writes_src      = (const int*)d_in[18];
    const int*   writes_dst      = (const int*)d_in[19];
    const int*   wb_src          = (const int*)d_in[20];
    const int*   wb_dst          = (const int*)d_in[21];
    const int*   cites_src       = (const int*)d_in[22];
    const int*   cites_dst       = (const int*)d_in[23];
    float* out = (float*)d_out;

    float *PA, *PP, *elA_aA, *erP_aA, *elP_aP, *erA_aP, *erP_aP;
    float *ft_w, *ft_wb, *ft_c, *rf_w, *rf_c, *nodeP;
    int *counts, *cursor, *offsets, *partials, *ssort;
    cudaGetSymbolAddress((void**)&PA, g_PA);
    cudaGetSymbolAddress((void**)&PP, g_PP);
    cudaGetSymbolAddress((void**)&elA_aA, g_elA_aA);
    cudaGetSymbolAddress((void**)&erP_aA, g_erP_aA);
    cudaGetSymbolAddress((void**)&elP_aP, g_elP_aP);
    cudaGetSymbolAddress((void**)&erA_aP, g_erA_aP);
    cudaGetSymbolAddress((void**)&erP_aP, g_erP_aP);
    cudaGetSymbolAddress((void**)&ft_w, g_ft_w);
    cudaGetSymbolAddress((void**)&ft_wb, g_ft_wb);
    cudaGetSymbolAddress((void**)&ft_c, g_ft_c);
    cudaGetSymbolAddress((void**)&rf_w, g_rf_w);
    cudaGetSymbolAddress((void**)&rf_c, g_rf_c);
    cudaGetSymbolAddress((void**)&nodeP, g_nodeP);
    cudaGetSymbolAddress((void**)&counts, g_counts);
    cudaGetSymbolAddress((void**)&cursor, g_cursor);
    cudaGetSymbolAddress((void**)&offsets, g_offsets);
    cudaGetSymbolAddress((void**)&partials, g_partials);
    cudaGetSymbolAddress((void**)&ssort, g_ssort);

    cudaFuncSetAttribute(gemm_multi, cudaFuncAttributeMaxDynamicSharedMemorySize, SMEM_BYTES);

    const int GG = (NA + BM - 1) / BM;          // 391
    const int EB = (EDG + 255) / 256;
    const int GB = (NA * 32 + 255) / 256;

    GemmJob jz = {};

    // author group: micro (+fused attn dots) and residual (with bias) -> out[:NA]
    {
        GemmJob ja = { feats_author, W_micro_author, PA, nullptr, nullptr,
                       attn_micro_a + 0,  elA_aA,
                       attn_micro_p + 32, erA_aP,
                       nullptr, nullptr };
        GemmJob jb = { feats_author, W_res_author, out, b_res_author, nullptr,
                       nullptr, nullptr, nullptr, nullptr, nullptr, nullptr };
        gemm_multi<<<GG, 256, SMEM_BYTES>>>(ja, jb, jz, 2, NA);
    }
    // paper group: micro (+3 fused attn dots), macro-node, residual -> out[NA:]
    {
        GemmJob ja = { feats_paper, W_micro_paper, PP, nullptr, nullptr,
                       attn_micro_a + 32, erP_aA,
                       attn_micro_p + 0,  elP_aP,
                       attn_micro_p + 32, erP_aP };
        GemmJob jb = { feats_paper, W_macro_node_p, nodeP, nullptr, nullptr,
                       nullptr, nullptr, nullptr, nullptr, nullptr, nullptr };
        GemmJob jc = { feats_paper, W_res_paper, out + (size_t)NA * KD, b_res_paper, nullptr,
                       nullptr, nullptr, nullptr, nullptr, nullptr, nullptr };
        gemm_multi<<<GG, 256, SMEM_BYTES>>>(ja, jb, jc, 3, NP);
    }

    // --- per-relation CSR + gather ---
    struct Rel { const int* src; const int* dst; const float* el; const float* er;
                 const float* P; float* ft; int n; };
    Rel rels[3] = {
        { writes_src, writes_dst, elA_aA, erP_aA, PA, ft_w,  NP },
        { wb_src,     wb_dst,     elP_aP, erA_aP, PP, ft_wb, NA },
        { cites_src,  cites_dst,  elP_aP, erP_aP, PP, ft_c,  NP },
    };
    for (int r = 0; r < 3; r++) {
        Rel& R = rels[r];
        cudaMemsetAsync(counts, 0, R.n * sizeof(int));
        cudaMemsetAsync(cursor, 0, R.n * sizeof(int));
        csr_hist<<<EB, 256>>>(R.dst, counts);
        scan_block<<<NBLK, 256>>>(counts, offsets, partials, R.n);
        scan_top<<<1, 256>>>(partials, NBLK);
        scan_add<<<NBLK, 256>>>(offsets, partials, R.n);
        csr_scatter<<<EB, 256>>>(R.src, R.dst, offsets, cursor, ssort);
        micro_gather<<<GB, 256>>>(ssort, offsets, R.el, R.er, R.P, R.ft, R.n);
    }

    // macro group: rf_w, rf_c, gated wb residual -> all in one launch
    {
        GemmJob ja = { ft_w, W_rel_writes, rf_w, nullptr, nullptr,
                       nullptr, nullptr, nullptr, nullptr, nullptr, nullptr };
        GemmJob jb = { ft_c, W_rel_cites, rf_c, nullptr, nullptr,
                       nullptr, nullptr, nullptr, nullptr, nullptr, nullptr };
        GemmJob jc = { ft_wb, W_rel_wb, out, nullptr, res_w_author,
                       nullptr, nullptr, nullptr, nullptr, nullptr, nullptr };
        gemm_multi<<<GG, 256, SMEM_BYTES>>>(ja, jb, jc, 3, NA);
    }

    // final paper fusion
    final_paper<<<NP, 256>>>(rf_w, rf_c, nodeP, attn_macro, res_w_paper, out);
}

// round 7
// speedup vs baseline: 2.6682x; 1.1251x over previous
#include <cuda_runtime.h>
#include <cstdint>
#include <math.h>

// ---------------- problem constants ----------------
#define NA 50000
#define NP 50000
#define EDG 400000
#define KH 8
#define DH 32
#define KD 256
#define SLOPE 0.2f

// GEMM tiling: block 128(M) x 256(N), 8 warps (2m x 4n), warp tile 64x64, BK=16
#define BM 128
#define BK 16
#define NKT (KD / BK)      // 16
#define LDK 20
#define LDBN 264
#define ASZ (128 * LDK)
#define BSZ (BK * LDBN)
#define SMEM_BYTES ((2 * ASZ + 2 * BSZ) * 4)   // 54272

#define NBLK 196           // ceil(50000/256)

// ---------------- device scratch ----------------
__device__ float g_PA[NA * KD];
__device__ float g_PP[NP * KD];

__device__ float g_elA_aA[NA * KH];
__device__ float g_erP_aA[NP * KH];
__device__ float g_elP_aP[NP * KH];
__device__ float g_erA_aP[NA * KH];
__device__ float g_erP_aP[NP * KH];

__device__ float g_ft_w[NP * KD];
__device__ float g_ft_wb[NA * KD];
__device__ float g_ft_c[NP * KD];

__device__ float g_rf_w[NP * KD];
__device__ float g_rf_c[NP * KD];
__device__ float g_nodeP[NP * KD];

// CSR scratch, one set per relation (built concurrently on side stream)
__device__ int g_counts[3][50000];
__device__ int g_cursor[3][50000];
__device__ int g_offsets[3][50001];
__device__ int g_partials[3][NBLK + 1];
__device__ int g_ssort[3][EDG];

// ---------------- helpers ----------------
__device__ __forceinline__ float leaky(float v) {
    return v > 0.f ? v : SLOPE * v;
}
__device__ __forceinline__ uint32_t f2tf32(float f) {
    uint32_t r;
    asm("cvt.rna.tf32.f32 %0, %1;" : "=r"(r) : "f"(f));
    return r;
}
__device__ __forceinline__ void mma_tf32(float c[4], uint32_t a0, uint32_t a1,
                                         uint32_t a2, uint32_t a3,
                                         uint32_t b0, uint32_t b1) {
    asm volatile(
        "mma.sync.aligned.m16n8k8.row.col.f32.tf32.tf32.f32 "
        "{%0,%1,%2,%3}, {%4,%5,%6,%7}, {%8,%9}, {%0,%1,%2,%3};"
        : "+f"(c[0]), "+f"(c[1]), "+f"(c[2]), "+f"(c[3])
        : "r"(a0), "r"(a1), "r"(a2), "r"(a3), "r"(b0), "r"(b1));
}

struct GemmJob {
    const float* A;
    const float* B;
    float*       C;
    const float* bias;
    const float* gate;
    const float* av0; float* ao0;
    const float* av1; float* ao1;
    const float* av2; float* ao2;
};

// ---------------- multi-job tf32 GEMM (unchanged from R6) ----------------
__global__ void __launch_bounds__(256, 1) gemm_multi(
    GemmJob j0, GemmJob j1, GemmJob j2, int nb, int M)
{
    extern __shared__ uint32_t smem[];
    const int tid = threadIdx.x;
    const int lane = tid & 31;
    const int wid = tid >> 5;
    const int wm = (wid & 1) * 64;
    const int wn = (wid >> 1) * 64;
    const int m0 = blockIdx.x * BM;

    const int qr = lane >> 2;
    const int qc = lane & 3;

    const int am = tid >> 1;
    const int aq = (tid & 1) * 8;
    const int bkr = tid >> 4;
    const int bnc = (tid & 15) * 16;

    float4 rA[2], rB[4];

    auto g_load = [&](int kt, const float* __restrict__ A, const float* __restrict__ B) {
        const int k0 = kt * BK;
        int row = m0 + am;
        if (row < M) {
            rA[0] = *(const float4*)&A[(size_t)row * KD + k0 + aq];
            rA[1] = *(const float4*)&A[(size_t)row * KD + k0 + aq + 4];
        } else {
            rA[0] = make_float4(0.f, 0.f, 0.f, 0.f);
            rA[1] = rA[0];
        }
        const float* bp = &B[(size_t)(k0 + bkr) * KD + bnc];
        rB[0] = *(const float4*)&bp[0];
        rB[1] = *(const float4*)&bp[4];
        rB[2] = *(const float4*)&bp[8];
        rB[3] = *(const float4*)&bp[12];
    };
    auto s_store = [&](int buf) {
        uint32_t* as = &smem[buf * ASZ + am * LDK + aq];
        uint4 v0, v1;
        v0.x = f2tf32(rA[0].x); v0.y = f2tf32(rA[0].y);
        v0.z = f2tf32(rA[0].z); v0.w = f2tf32(rA[0].w);
        v1.x = f2tf32(rA[1].x); v1.y = f2tf32(rA[1].y);
        v1.z = f2tf32(rA[1].z); v1.w = f2tf32(rA[1].w);
        *(uint4*)&as[0] = v0;
        *(uint4*)&as[4] = v1;
        uint32_t* bs = &smem[2 * ASZ + buf * BSZ + bkr * LDBN + bnc];
#pragma unroll
        for (int q = 0; q < 4; q++) {
            uint4 w;
            w.x = f2tf32(((const float*)&rB[q])[0]);
            w.y = f2tf32(((const float*)&rB[q])[1]);
            w.z = f2tf32(((const float*)&rB[q])[2]);
            w.w = f2tf32(((const float*)&rB[q])[3]);
            *(uint4*)&bs[q * 4] = w;
        }
    };

#pragma unroll
    for (int o = 0; o < 3; o++) {
        if (o >= nb) break;
        const GemmJob J = (o == 0) ? j0 : (o == 1) ? j1 : j2;

        float acc[4][8][4];
#pragma unroll
        for (int mi = 0; mi < 4; mi++)
#pragma unroll
            for (int ni = 0; ni < 8; ni++)
#pragma unroll
                for (int r = 0; r < 4; r++) acc[mi][ni][r] = 0.f;

        g_load(0, J.A, J.B);
        s_store(0);
        __syncthreads();

        for (int kt = 0; kt < NKT; kt++) {
            const int cur = kt & 1;
            if (kt + 1 < NKT) g_load(kt + 1, J.A, J.B);

            const uint32_t* asb = &smem[cur * ASZ];
            const uint32_t* bsb = &smem[2 * ASZ + cur * BSZ];
#pragma unroll
            for (int ks = 0; ks < BK; ks += 8) {
                uint32_t a[4][4], b[8][2];
#pragma unroll
                for (int mi = 0; mi < 4; mi++) {
                    int r0 = wm + mi * 16 + qr;
                    a[mi][0] = asb[r0 * LDK + ks + qc];
                    a[mi][1] = asb[(r0 + 8) * LDK + ks + qc];
                    a[mi][2] = asb[r0 * LDK + ks + qc + 4];
                    a[mi][3] = asb[(r0 + 8) * LDK + ks + qc + 4];
                }
#pragma unroll
                for (int ni = 0; ni < 8; ni++) {
                    int c0 = wn + ni * 8 + qr;
                    b[ni][0] = bsb[(ks + qc) * LDBN + c0];
                    b[ni][1] = bsb[(ks + qc + 4) * LDBN + c0];
                }
#pragma unroll
                for (int mi = 0; mi < 4; mi++)
#pragma unroll
                    for (int ni = 0; ni < 8; ni++)
                        mma_tf32(acc[mi][ni], a[mi][0], a[mi][1], a[mi][2], a[mi][3],
                                 b[ni][0], b[ni][1]);
            }

            if (kt + 1 < NKT) {
                s_store(1 - cur);
                __syncthreads();
            }
        }

        if (J.av0) {
            const float* avs[3] = { J.av0, J.av1, J.av2 };
            float*       aos[3] = { J.ao0, J.ao1, J.ao2 };
            const int h0 = wn >> 5;
#pragma unroll
            for (int t = 0; t < 3; t++) {
                const float* av = avs[t];
                if (!av) break;
                float* ao = aos[t];
                float c0[8], c1[8];
#pragma unroll
                for (int ni = 0; ni < 8; ni++) {
                    int col = wn + ni * 8 + qc * 2;
                    int idx = (col >> 5) * 64 + (col & 31);
                    c0[ni] = av[idx];
                    c1[ni] = av[idx + 1];
                }
#pragma unroll
                for (int mi = 0; mi < 4; mi++) {
#pragma unroll
                    for (int half = 0; half < 2; half++) {
                        float pa = 0.f, pb = 0.f;
#pragma unroll
                        for (int ni = 0; ni < 4; ni++)
                            pa += acc[mi][ni][half * 2] * c0[ni]
                                + acc[mi][ni][half * 2 + 1] * c1[ni];
#pragma unroll
                        for (int ni = 4; ni < 8; ni++)
                            pb += acc[mi][ni][half * 2] * c0[ni]
                                + acc[mi][ni][half * 2 + 1] * c1[ni];
                        pa += __shfl_xor_sync(0xffffffffu, pa, 1);
                        pa += __shfl_xor_sync(0xffffffffu, pa, 2);
                        pb += __shfl_xor_sync(0xffffffffu, pb, 1);
                        pb += __shfl_xor_sync(0xffffffffu, pb, 2);
                        int row = m0 + wm + mi * 16 + qr + half * 8;
                        if (qc == 0 && row < M) {
                            ao[row * KH + h0]     = pa;
                            ao[row * KH + h0 + 1] = pb;
                        }
                    }
                }
            }
        }

        float g = 0.f;
        if (J.gate) g = 1.f / (1.f + __expf(-J.gate[0]));

#pragma unroll
        for (int mi = 0; mi < 4; mi++) {
#pragma unroll
            for (int half = 0; half < 2; half++) {
                int row = m0 + wm + mi * 16 + qr + half * 8;
                if (row >= M) continue;
                float* dst = &J.C[(size_t)row * KD + wn];
#pragma unroll
                for (int ni = 0; ni < 8; ni++) {
                    int col = ni * 8 + qc * 2;
                    float2 v;
                    v.x = acc[mi][ni][half * 2 + 0];
                    v.y = acc[mi][ni][half * 2 + 1];
                    if (J.bias) {
                        v.x += J.bias[wn + col + 0];
                        v.y += J.bias[wn + col + 1];
                    }
                    if (J.gate) {
                        float2 prev = *(const float2*)&dst[col];
                        v.x = g * v.x + (1.f - g) * prev.x;
                        v.y = g * v.y + (1.f - g) * prev.y;
                    }
                    *(float2*)&dst[col] = v;
                }
            }
        }
        __syncthreads();
    }
}

// ---------------- CSR build ----------------
__global__ void csr_hist(const int* __restrict__ dst, int* __restrict__ counts)
{
    int e = blockIdx.x * blockDim.x + threadIdx.x;
    if (e < EDG) atomicAdd(&counts[dst[e]], 1);
}

__global__ void scan_block(const int* __restrict__ in, int* __restrict__ out,
                           int* __restrict__ partials, int n)
{
    __shared__ int wsum[8];
    int i = blockIdx.x * 256 + threadIdx.x;
    int lane = threadIdx.x & 31, wid = threadIdx.x >> 5;
    int v = (i < n) ? in[i] : 0;
    int x = v;
#pragma unroll
    for (int o = 1; o < 32; o <<= 1) {
        int t = __shfl_up_sync(0xffffffffu, x, o);
        if (lane >= o) x += t;
    }
    if (lane == 31) wsum[wid] = x;
    __syncthreads();
    if (wid == 0) {
        int w = (lane < 8) ? wsum[lane] : 0;
#pragma unroll
        for (int o = 1; o < 8; o <<= 1) {
            int t = __shfl_up_sync(0xffffffffu, w, o);
            if (lane >= o) w += t;
        }
        if (lane < 8) wsum[lane] = w;
    }
    __syncthreads();
    int wpre = (wid > 0) ? wsum[wid - 1] : 0;
    if (i < n) out[i] = wpre + x - v;
    if (threadIdx.x == 0) partials[blockIdx.x] = wsum[7];
}

__global__ void scan_top(int* __restrict__ partials, int nb)
{
    __shared__ int wsum[8];
    int i = threadIdx.x;
    int lane = i & 31, wid = i >> 5;
    int v = (i < nb) ? partials[i] : 0;
    int x = v;
#pragma unroll
    for (int o = 1; o < 32; o <<= 1) {
        int t = __shfl_up_sync(0xffffffffu, x, o);
        if (lane >= o) x += t;
    }
    if (lane == 31) wsum[wid] = x;
    __syncthreads();
    if (wid == 0) {
        int w = (lane < 8) ? wsum[lane] : 0;
#pragma unroll
        for (int o = 1; o < 8; o <<= 1) {
            int t = __shfl_up_sync(0xffffffffu, w, o);
            if (lane >= o) w += t;
        }
        if (lane < 8) wsum[lane] = w;
    }
    __syncthreads();
    int wpre = (wid > 0) ? wsum[wid - 1] : 0;
    if (i < nb) partials[i] = wpre + x - v;
    if (i == 0) partials[nb] = wsum[7];
}

__global__ void scan_add(int* __restrict__ offsets, const int* __restrict__ partials, int n)
{
    int i = blockIdx.x * 256 + threadIdx.x;
    if (i < n) offsets[i] += partials[blockIdx.x];
    if (i == 0) offsets[n] = partials[gridDim.x];
}

__global__ void csr_scatter(const int* __restrict__ src, const int* __restrict__ dst,
                            const int* __restrict__ offsets, int* __restrict__ cursor,
                            int* __restrict__ ssort)
{
    int e = blockIdx.x * blockDim.x + threadIdx.x;
    if (e >= EDG) return;
    int d = dst[e];
    int pos = offsets[d] + atomicAdd(&cursor[d], 1);
    ssort[pos] = src[e];
}

// ---------------- fused micro gather: softmax + weighted sum + relu ----------------
__global__ void micro_gather(const int* __restrict__ ssort, const int* __restrict__ offsets,
                             const float* __restrict__ el, const float* __restrict__ er,
                             const float* __restrict__ Psrc, float* __restrict__ ft, int n_dst)
{
    int d = (blockIdx.x * blockDim.x + threadIdx.x) >> 5;
    int lane = threadIdx.x & 31;
    if (d >= n_dst) return;
    int beg = offsets[d], end = offsets[d + 1];
    float* dstp = &ft[(size_t)d * KD + lane * 8];
    if (beg == end) {
        float4 z = make_float4(0.f, 0.f, 0.f, 0.f);
        *(float4*)dstp = z;
        *(float4*)(dstp + 4) = z;
        return;
    }
    const int h8 = lane & 7;
    float erh = er[d * KH + h8];   // er for head h8 (valid for all lanes)

    // pass 1: per-head max, 4 edges per iteration (lane = 8*sub + head)
    float mx = -1e30f;
    {
        int sub = lane >> 3;
        for (int i = beg; i < end; i += 4) {
            int e = i + sub;
            if (e < end) {
                int s = ssort[e];
                mx = fmaxf(mx, leaky(el[s * KH + h8] + erh));
            }
        }
        mx = fmaxf(mx, __shfl_xor_sync(0xffffffffu, mx, 8));
        mx = fmaxf(mx, __shfl_xor_sync(0xffffffffu, mx, 16));
        // now every lane holds the max for head (lane & 7)
    }

    // pass 2: exp weights + weighted feature accumulation, 2 edges per iteration
    const int hk = lane >> 2;   // head owning this lane's 8 output columns
    float acc[8] = {0.f, 0.f, 0.f, 0.f, 0.f, 0.f, 0.f, 0.f};
    float se = 0.f;
    int i = beg;
    for (; i + 2 <= end; i += 2) {
        int s0 = ssort[i], s1 = ssort[i + 1];
        float w0 = 0.f, w1 = 0.f;
        if (lane < KH) {
            w0 = __expf(leaky(el[s0 * KH + lane] + erh) - mx);
            w1 = __expf(leaky(el[s1 * KH + lane] + erh) - mx);
            se += w0 + w1;
        }
        float wk0 = __shfl_sync(0xffffffffu, w0, hk);
        float wk1 = __shfl_sync(0xffffffffu, w1, hk);
        const float4* p0 = (const float4*)&Psrc[(size_t)s0 * KD + lane * 8];
        const float4* p1 = (const float4*)&Psrc[(size_t)s1 * KD + lane * 8];
        float4 a0 = p0[0], a1 = p0[1], b0 = p1[0], b1 = p1[1];
        acc[0] = fmaf(wk0, a0.x, acc[0]); acc[0] = fmaf(wk1, b0.x, acc[0]);
        acc[1] = fmaf(wk0, a0.y, acc[1]); acc[1] = fmaf(wk1, b0.y, acc[1]);
        acc[2] = fmaf(wk0, a0.z, acc[2]); acc[2] = fmaf(wk1, b0.z, acc[2]);
        acc[3] = fmaf(wk0, a0.w, acc[3]); acc[3] = fmaf(wk1, b0.w, acc[3]);
        acc[4] = fmaf(wk0, a1.x, acc[4]); acc[4] = fmaf(wk1, b1.x, acc[4]);
        acc[5] = fmaf(wk0, a1.y, acc[5]); acc[5] = fmaf(wk1, b1.y, acc[5]);
        acc[6] = fmaf(wk0, a1.z, acc[6]); acc[6] = fmaf(wk1, b1.z, acc[6]);
        acc[7] = fmaf(wk0, a1.w, acc[7]); acc[7] = fmaf(wk1, b1.w, acc[7]);
    }
    if (i < end) {
        int s0 = ssort[i];
        float w0 = 0.f;
        if (lane < KH) {
            w0 = __expf(leaky(el[s0 * KH + lane] + erh) - mx);
            se += w0;
        }
        float wk0 = __shfl_sync(0xffffffffu, w0, hk);
        const float4* p0 = (const float4*)&Psrc[(size_t)s0 * KD + lane * 8];
        float4 a0 = p0[0], a1 = p0[1];
        acc[0] = fmaf(wk0, a0.x, acc[0]);
        acc[1] = fmaf(wk0, a0.y, acc[1]);
        acc[2] = fmaf(wk0, a0.z, acc[2]);
        acc[3] = fmaf(wk0, a0.w, acc[3]);
        acc[4] = fmaf(wk0, a1.x, acc[4]);
        acc[5] = fmaf(wk0, a1.y, acc[5]);
        acc[6] = fmaf(wk0, a1.z, acc[6]);
        acc[7] = fmaf(wk0, a1.w, acc[7]);
    }
    float inv = 1.f / __shfl_sync(0xffffffffu, se, hk);
    float4 o0, o1;
    o0.x = fmaxf(acc[0] * inv, 0.f);
    o0.y = fmaxf(acc[1] * inv, 0.f);
    o0.z = fmaxf(acc[2] * inv, 0.f);
    o0.w = fmaxf(acc[3] * inv, 0.f);
    o1.x = fmaxf(acc[4] * inv, 0.f);
    o1.y = fmaxf(acc[5] * inv, 0.f);
    o1.z = fmaxf(acc[6] * inv, 0.f);
    o1.w = fmaxf(acc[7] * inv, 0.f);
    *(float4*)dstp = o0;
    *(float4*)(dstp + 4) = o1;
}

// ---------------- final paper ----------------
__global__ void final_paper(const float* __restrict__ rfw, const float* __restrict__ rfc,
                            const float* __restrict__ nodep, const float* __restrict__ attnM,
                            const float* __restrict__ resw, float* __restrict__ out)
{
    int n = blockIdx.x;
    int k = threadIdx.x >> 5;
    int lane = threadIdx.x & 31;
    size_t idx = (size_t)n * KD + k * DH + lane;
    float np = nodep[idx], rw = rfw[idx], rc = rfc[idx];
    float a1 = attnM[k * 64 + lane];
    float a2 = attnM[k * 64 + 32 + lane];
    float sw = a1 * np + a2 * rw;
    float sc = a1 * np + a2 * rc;
#pragma unroll
    for (int s = 16; s > 0; s >>= 1) {
        sw += __shfl_xor_sync(0xffffffffu, sw, s);
        sc += __shfl_xor_sync(0xffffffffu, sc, s);
    }
    sw = leaky(sw);
    sc = leaky(sc);
    float mx = fmaxf(sw, sc);
    float ew = __expf(sw - mx), ec = __expf(sc - mx);
    float aw = ew / (ew + ec);
    float val = aw * rw + (1.f - aw) * rc;
    float g = 1.f / (1.f + __expf(-resw[0]));
    size_t o = (size_t)NA * KD + idx;
    out[o] = g * val + (1.f - g) * out[o];
}

// ---------------- launch ----------------
extern "C" void kernel_launch(void* const* d_in, const int* in_sizes, int n_in,
                              void* d_out, int out_size)
{
    const float* feats_author    = (const float*)d_in[0];
    const float* feats_paper     = (const float*)d_in[1];
    const float* W_micro_author  = (const float*)d_in[2];
    const float* W_micro_paper   = (const float*)d_in[3];
    const float* attn_micro_a    = (const float*)d_in[4];
    const float* attn_micro_p    = (const float*)d_in[5];
    const float* W_macro_node_p  = (const float*)d_in[7];
    const float* W_rel_writes    = (const float*)d_in[8];
    const float* W_rel_wb        = (const float*)d_in[9];
    const float* W_rel_cites     = (const float*)d_in[10];
    const float* attn_macro      = (const float*)d_in[11];
    const float* W_res_author    = (const float*)d_in[12];
    const float* b_res_author    = (const float*)d_in[13];
    const float* W_res_paper     = (const float*)d_in[14];
    const float* b_res_paper     = (const float*)d_in[15];
    const float* res_w_author    = (const float*)d_in[16];
    const float* res_w_paper     = (const float*)d_in[17];
    const int*   writes_src      = (const int*)d_in[18];
    const int*   writes_dst      = (const int*)d_in[19];
    const int*   wb_src          = (const int*)d_in[20];
    const int*   wb_dst          = (const int*)d_in[21];
    const int*   cites_src       = (const int*)d_in[22];
    const int*   cites_dst       = (const int*)d_in[23];
    float* out = (float*)d_out;

    float *PA, *PP, *elA_aA, *erP_aA, *elP_aP, *erA_aP, *erP_aP;
    float *ft_w, *ft_wb, *ft_c, *rf_w, *rf_c, *nodeP;
    int *counts, *cursor, *offsets, *partials, *ssort;
    cudaGetSymbolAddress((void**)&PA, g_PA);
    cudaGetSymbolAddress((void**)&PP, g_PP);
    cudaGetSymbolAddress((void**)&elA_aA, g_elA_aA);
    cudaGetSymbolAddress((void**)&erP_aA, g_erP_aA);
    cudaGetSymbolAddress((void**)&elP_aP, g_elP_aP);
    cudaGetSymbolAddress((void**)&erA_aP, g_erA_aP);
    cudaGetSymbolAddress((void**)&erP_aP, g_erP_aP);
    cudaGetSymbolAddress((void**)&ft_w, g_ft_w);
    cudaGetSymbolAddress((void**)&ft_wb, g_ft_wb);
    cudaGetSymbolAddress((void**)&ft_c, g_ft_c);
    cudaGetSymbolAddress((void**)&rf_w, g_rf_w);
    cudaGetSymbolAddress((void**)&rf_c, g_rf_c);
    cudaGetSymbolAddress((void**)&nodeP, g_nodeP);
    cudaGetSymbolAddress((void**)&counts, g_counts);
    cudaGetSymbolAddress((void**)&cursor, g_cursor);
    cudaGetSymbolAddress((void**)&offsets, g_offsets);
    cudaGetSymbolAddress((void**)&partials, g_partials);
    cudaGetSymbolAddress((void**)&ssort, g_ssort);

    // one-time stream/event creation (resources only; work is identical every call)
    static cudaStream_t s2 = nullptr;
    static cudaEvent_t evFork = nullptr, evMicro = nullptr, evG[3] = {};
    if (!s2) {
        cudaStreamCreateWithFlags(&s2, cudaStreamNonBlocking);
        cudaEventCreateWithFlags(&evFork, cudaEventDisableTiming);
        cudaEventCreateWithFlags(&evMicro, cudaEventDisableTiming);
        for (int r = 0; r < 3; r++)
            cudaEventCreateWithFlags(&evG[r], cudaEventDisableTiming);
    }

    cudaFuncSetAttribute(gemm_multi, cudaFuncAttributeMaxDynamicSharedMemorySize, SMEM_BYTES);

    const int GG = (NA + BM - 1) / BM;          // 391
    const int EB = (EDG + 255) / 256;
    const int GB = (NA * 32 + 255) / 256;

    GemmJob jz = {};

    struct Rel { const int* src; const int* dst; const float* el; const float* er;
                 const float* P; float* ft; int n; };
    Rel rels[3] = {
        { writes_src, writes_dst, elA_aA, erP_aA, PA, ft_w,  NP },
        { wb_src,     wb_dst,     elP_aP, erA_aP, PP, ft_wb, NA },
        { cites_src,  cites_dst,  elP_aP, erP_aP, PP, ft_c,  NP },
    };

    // ---- fork side stream for CSR builds (edge-only, independent of GEMMs) ----
    cudaEventRecord(evFork, 0);
    cudaStreamWaitEvent(s2, evFork, 0);
    for (int r = 0; r < 3; r++) {
        Rel& R = rels[r];
        int* cnt = counts  + r * 50000;
        int* cur = cursor  + r * 50000;
        int* off = offsets + r * 50001;
        int* par = partials + r * (NBLK + 1);
        int* srt = ssort   + r * EDG;
        cudaMemsetAsync(cnt, 0, R.n * sizeof(int), s2);
        cudaMemsetAsync(cur, 0, R.n * sizeof(int), s2);
        csr_hist<<<EB, 256, 0, s2>>>(R.dst, cnt);
        scan_block<<<NBLK, 256, 0, s2>>>(cnt, off, par, R.n);
        scan_top<<<1, 256, 0, s2>>>(par, NBLK);
        scan_add<<<NBLK, 256, 0, s2>>>(off, par, R.n);
        csr_scatter<<<EB, 256, 0, s2>>>(R.src, R.dst, off, cur, srt);
    }

    // ---- main stream: micro projections first (gathers depend on them) ----
    {
        GemmJob ja = { feats_author, W_micro_author, PA, nullptr, nullptr,
                       attn_micro_a + 0,  elA_aA,
                       attn_micro_p + 32, erA_aP,
                       nullptr, nullptr };
        gemm_multi<<<GG, 256, SMEM_BYTES>>>(ja, jz, jz, 1, NA);
    }
    {
        GemmJob ja = { feats_paper, W_micro_paper, PP, nullptr, nullptr,
                       attn_micro_a + 32, erP_aA,
                       attn_micro_p + 0,  elP_aP,
                       attn_micro_p + 32, erP_aP };
        gemm_multi<<<GG, 256, SMEM_BYTES>>>(ja, jz, jz, 1, NP);
    }
    cudaEventRecord(evMicro, 0);

    // ---- side stream: gathers (after micro projections) ----
    cudaStreamWaitEvent(s2, evMicro, 0);
    for (int r = 0; r < 3; r++) {
        Rel& R = rels[r];
        int* off = offsets + r * 50001;
        int* srt = ssort   + r * EDG;
        micro_gather<<<GB, 256, 0, s2>>>(srt, off, R.el, R.er, R.P, R.ft, R.n);
        cudaEventRecord(evG[r], s2);
    }

    // ---- main stream: independent GEMMs overlap with gathers ----
    {
        GemmJob ja = { feats_author, W_res_author, out, b_res_author, nullptr,
                       nullptr, nullptr, nullptr, nullptr, nullptr, nullptr };
        GemmJob jb = { feats_paper, W_macro_node_p, nodeP, nullptr, nullptr,
                       nullptr, nullptr, nullptr, nullptr, nullptr, nullptr };
        GemmJob jc = { feats_paper, W_res_paper, out + (size_t)NA * KD, b_res_paper, nullptr,
                       nullptr, nullptr, nullptr, nullptr, nullptr, nullptr };
        gemm_multi<<<GG, 256, SMEM_BYTES>>>(ja, jb, jc, 3, NA);
    }

    // ---- macro projections, each gated on its gather ----
    cudaStreamWaitEvent(0, evG[0], 0);
    {
        GemmJob ja = { ft_w, W_rel_writes, rf_w, nullptr, nullptr,
                       nullptr, nullptr, nullptr, nullptr, nullptr, nullptr };
        gemm_multi<<<GG, 256, SMEM_BYTES>>>(ja, jz, jz, 1, NP);
    }
    cudaStreamWaitEvent(0, evG[2], 0);
    {
        GemmJob ja = { ft_c, W_rel_cites, rf_c, nullptr, nullptr,
                       nullptr, nullptr, nullptr, nullptr, nullptr, nullptr };
        gemm_multi<<<GG, 256, SMEM_BYTES>>>(ja, jz, jz, 1, NP);
    }
    cudaStreamWaitEvent(0, evG[1], 0);
    {
        GemmJob ja = { ft_wb, W_rel_wb, out, nullptr, res_w_author,
                       nullptr, nullptr, nullptr, nullptr, nullptr, nullptr };
        gemm_multi<<<GG, 256, SMEM_BYTES>>>(ja, jz, jz, 1, NA);
    }

    // ---- final paper fusion ----
    final_paper<<<NP, 256>>>(rf_w, rf_c, nodeP, attn_macro, res_w_paper, out);
}